// round 11
// baseline (speedup 1.0000x reference)
#include <cuda_runtime.h>
#include <cuda_bf16.h>
#include <cuda_fp16.h>
#include <cstdint>

// Problem constants (DiffnapsNet_42030549959310)
#define BV 4096   // batch
#define DV 8192   // data dim
#define HV 4096   // hidden
#define LV 128    // labels

#define FP8_ONE 0x38u     // e4m3 1.0
#define BF16_ONE 0x3F80u  // bf16 1.0

// ---------------------------------------------------------------------------
// Scratch (device globals; no allocation allowed)
// ---------------------------------------------------------------------------
__device__ __align__(16) uint8_t  g_x8[(size_t)BV * DV];    // [B][D] e4m3
__device__ __align__(16) uint8_t  g_w8[(size_t)HV * DV];    // [H][D] e4m3
__device__ __align__(16) uint8_t  g_wT8[(size_t)DV * HV];   // [D][H] e4m3
__device__ __align__(16) uint8_t  g_z8[(size_t)BV * HV];    // [B][H] e4m3
__device__ __align__(16) uint16_t g_zbf[(size_t)BV * HV];   // [B][H] bf16
__device__ __align__(16) uint16_t g_whi[(size_t)LV * HV];   // [L][H] bf16 hi
__device__ __align__(16) uint16_t g_wlo[(size_t)LV * HV];   // [L][H] bf16 lo

// ---------------------------------------------------------------------------
// PTX helpers (family-compatible: sm_80/89 features only)
// ---------------------------------------------------------------------------
__device__ __forceinline__ uint32_t smem_u32(const void* p) {
    uint32_t a;
    asm("{ .reg .u64 t; cvta.to.shared.u64 t, %1; cvt.u32.u64 %0, t; }"
        : "=r"(a) : "l"(p));
    return a;
}
__device__ __forceinline__ void cp16(uint32_t dst, const void* src) {
    asm volatile("cp.async.cg.shared.global [%0], [%1], 16;"
                 :: "r"(dst), "l"(src) : "memory");
}
#define CP_COMMIT() asm volatile("cp.async.commit_group;" ::: "memory")
#define CP_WAIT(n)  asm volatile("cp.async.wait_group %0;" :: "n"(n) : "memory")

__device__ __forceinline__ void ldm_x4(uint32_t (&r)[4], uint32_t addr) {
    asm volatile("ldmatrix.sync.aligned.m8n8.x4.shared.b16 {%0,%1,%2,%3}, [%4];"
                 : "=r"(r[0]), "=r"(r[1]), "=r"(r[2]), "=r"(r[3]) : "r"(addr));
}
// fp8 x fp8 -> fp16 accumulator (2 C regs): exact for integer counts <= 2048;
// larger counts stay >> threshold so no threshold decision can flip.
__device__ __forceinline__ void mma_fp8_h(uint32_t (&c)[2], const uint32_t (&a)[4],
                                          uint32_t b0, uint32_t b1) {
    asm volatile(
        "mma.sync.aligned.m16n8k32.row.col.f16.e4m3.e4m3.f16 "
        "{%0,%1}, {%2,%3,%4,%5}, {%6,%7}, {%0,%1};"
        : "+r"(c[0]), "+r"(c[1])
        : "r"(a[0]), "r"(a[1]), "r"(a[2]), "r"(a[3]), "r"(b0), "r"(b1));
}
__device__ __forceinline__ void mma_bf16(float (&c)[4], const uint32_t (&a)[4],
                                         uint32_t b0, uint32_t b1) {
    asm volatile(
        "mma.sync.aligned.m16n8k16.row.col.f32.bf16.bf16.f32 "
        "{%0,%1,%2,%3}, {%4,%5,%6,%7}, {%8,%9}, {%0,%1,%2,%3};"
        : "+f"(c[0]), "+f"(c[1]), "+f"(c[2]), "+f"(c[3])
        : "r"(a[0]), "r"(a[1]), "r"(a[2]), "r"(a[3]), "r"(b0), "r"(b1));
}

// ---------------------------------------------------------------------------
// Conversions
// ---------------------------------------------------------------------------
__global__ void cvt_fp8_kernel(const float* __restrict__ src,
                               uint32_t* __restrict__ dst, int n4) {
    int i = blockIdx.x * blockDim.x + threadIdx.x;
    if (i < n4) {
        float4 v = ((const float4*)src)[i];
        uint32_t w = (v.x > 0.5f ? FP8_ONE : 0u) | (v.y > 0.5f ? FP8_ONE << 8 : 0u) |
                     (v.z > 0.5f ? FP8_ONE << 16 : 0u) | (v.w > 0.5f ? FP8_ONE << 24 : 0u);
        dst[i] = w;
    }
}

// One pass over enc_weight -> both w8 (row-major) and wT8 (transposed).
__global__ void cvt_w_both_kernel(const float* __restrict__ w,
                                  uint8_t* __restrict__ w8,
                                  uint8_t* __restrict__ wT) {
    int d  = blockIdx.x * blockDim.x + threadIdx.x;  // 0..DV-1
    int hw = blockIdx.y;                             // 0..HV/32-1
    const float* col = w + (size_t)hw * 32 * DV + d;
    uint32_t wd[8];
#pragma unroll
    for (int q = 0; q < 8; q++) {
        uint32_t v = 0;
#pragma unroll
        for (int c = 0; c < 4; c++) {
            bool b = col[(size_t)(q * 4 + c) * DV] > 0.5f;
            if (b) v |= FP8_ONE << (c * 8);
            w8[(size_t)(hw * 32 + q * 4 + c) * DV + d] = b ? (uint8_t)FP8_ONE : 0;
        }
        wd[q] = v;
    }
    uint4* dst = (uint4*)(wT + (size_t)d * HV + hw * 32);
    dst[0] = make_uint4(wd[0], wd[1], wd[2], wd[3]);
    dst[1] = make_uint4(wd[4], wd[5], wd[6], wd[7]);
}

// Exact bf16 split of classifier weights: w = hi + lo
__global__ void cvt_wsplit_kernel(const float* __restrict__ w,
                                  uint16_t* __restrict__ whi,
                                  uint16_t* __restrict__ wlo, int n) {
    int i = blockIdx.x * blockDim.x + threadIdx.x;
    if (i < n) {
        float v = w[i];
        __nv_bfloat16 h = __float2bfloat16(v);
        float r = v - __bfloat162float(h);
        __nv_bfloat16 l = __float2bfloat16(r);
        whi[i] = *(uint16_t*)&h;
        wlo[i] = *(uint16_t*)&l;
    }
}

// ---------------------------------------------------------------------------
// FP8 mma.sync GEMM, fp16 accumulators.
// CTA tile 128(M) x 256(N), 256 threads = 8 warps in 2(m) x 4(n) grid,
// warp tile 64x64 (Mt=4, Nt=8).  128-byte K-chunks, 2-stage double buffer,
// ONE barrier per chunk (64 for K=8192, 32 for K=4096).
// Smem row stride 144B: rows start 4 banks apart -> the 8-row x 16B ldmatrix
// access covers all 32 banks exactly once (conflict-free, no swizzle).
// ---------------------------------------------------------------------------
#define KLDT 144
#define KATILE (128 * KLDT)          // 18432
#define KBTILE (256 * KLDT)          // 36864
#define KSTAGE (KATILE + KBTILE)     // 55296
#define GEMM_SMEM (2 * KSTAGE)       // 110592

template <int KB, bool WRITE_AUX>
__global__ __launch_bounds__(256, 2) void fp8_mma_gemm_kernel(
    const uint8_t* __restrict__ A, const uint8_t* __restrict__ Bm,
    const float* __restrict__ bias, float* __restrict__ Cf,
    uint8_t* __restrict__ C8, uint16_t* __restrict__ Cbf, int Ntot) {
    constexpr int NCH = KB / 128;
    extern __shared__ __align__(16) uint8_t smem[];
    const uint32_t s0 = smem_u32(smem);

    const int tid  = threadIdx.x;
    const int lane = tid & 31;
    const int wid  = tid >> 5;
    const int wm   = wid >> 2;   // 0..1 : m offset wm*64
    const int wn   = wid & 3;    // 0..3 : n offset wn*64
    const int m0   = blockIdx.y * 128;
    const int n0   = blockIdx.x * 256;

    // global->smem cp.async mapping: row = (tid>>3)+32p, 16B chunk q = tid&7
    const int crow = tid >> 3;        // 0..31
    const int cq   = (tid & 7) * 16;  // 0..112
    const uint8_t* gA = A + (size_t)(m0 + crow) * KB + cq;
    const uint8_t* gB = Bm + (size_t)(n0 + crow) * KB + cq;
    const uint32_t wAo = crow * KLDT + cq;
    const uint32_t wBo = KATILE + crow * KLDT + cq;

    // ldmatrix read bases (mapping validated in R7-R10; only stride changed)
    const uint32_t rdA0 = s0 +
        (wm * 64 + (lane & 7) + ((lane >> 3) & 1) * 8) * KLDT + (lane >> 4) * 16;
    const uint32_t rdB0 = s0 + KATILE +
        (wn * 64 + (lane & 7) + ((lane >> 4) & 1) * 8) * KLDT + ((lane >> 3) & 1) * 16;

    uint32_t acc[4][8][2];   // fp16x2 accumulators, Mt=4 x Nt=8
#pragma unroll
    for (int mt = 0; mt < 4; mt++)
#pragma unroll
        for (int nt = 0; nt < 8; nt++) { acc[mt][nt][0] = 0u; acc[mt][nt][1] = 0u; }

    auto issue = [&](int ch, int st) {
        const uint32_t base = s0 + (uint32_t)st * KSTAGE;
        const int kc = ch * 128;
#pragma unroll
        for (int p = 0; p < 4; p++)
            cp16(base + wAo + p * 32 * KLDT, gA + (size_t)(p * 32) * KB + kc);
#pragma unroll
        for (int p = 0; p < 8; p++)
            cp16(base + wBo + p * 32 * KLDT, gB + (size_t)(p * 32) * KB + kc);
        CP_COMMIT();
    };
    issue(0, 0);

    for (int ch = 0; ch < NCH; ch++) {
        CP_WAIT(0);        // chunk ch resident (its load overlapped compute ch-1)
        __syncthreads();   // all warps: chunk ch visible, stage (ch+1)&1 reads done
        if (ch + 1 < NCH) issue(ch + 1, (ch + 1) & 1);

        const uint32_t off = (uint32_t)(ch & 1) * KSTAGE;
#pragma unroll
        for (int ks = 0; ks < 4; ks++) {
            uint32_t bf[8][2];
#pragma unroll
            for (int nt2 = 0; nt2 < 4; nt2++) {
                uint32_t t[4];
                ldm_x4(t, rdB0 + off + nt2 * 16 * KLDT + ks * 32);
                bf[2 * nt2][0] = t[0]; bf[2 * nt2][1] = t[1];
                bf[2 * nt2 + 1][0] = t[2]; bf[2 * nt2 + 1][1] = t[3];
            }
#pragma unroll
            for (int mt = 0; mt < 4; mt++) {
                uint32_t af[4];
                ldm_x4(af, rdA0 + off + mt * 16 * KLDT + ks * 32);
#pragma unroll
                for (int nt = 0; nt < 8; nt++)
                    mma_fp8_h(acc[mt][nt], af, bf[nt][0], bf[nt][1]);
            }
        }
    }

    // epilogue: unpack fp16 counts, threshold with per-column bias
    {
        const int g  = lane >> 2;
        const int tg = lane & 3;
        const int cbase = n0 + wn * 64 + tg * 2;
        float bx[8], by[8];
#pragma unroll
        for (int nt = 0; nt < 8; nt++) {
            bx[nt] = bias[cbase + nt * 8];
            by[nt] = bias[cbase + nt * 8 + 1];
        }
#pragma unroll
        for (int mt = 0; mt < 4; mt++) {
            const int r0 = m0 + wm * 64 + mt * 16 + g;
            const int r1 = r0 + 8;
#pragma unroll
            for (int nt = 0; nt < 8; nt++) {
                const int c = cbase + nt * 8;
                __half2 h0 = *(__half2*)&acc[mt][nt][0];
                __half2 h1 = *(__half2*)&acc[mt][nt][1];
                float v00 = (__low2float(h0) + bx[nt] > 1.0f) ? 1.0f : 0.0f;
                float v01 = (__high2float(h0) + by[nt] > 1.0f) ? 1.0f : 0.0f;
                float v10 = (__low2float(h1) + bx[nt] > 1.0f) ? 1.0f : 0.0f;
                float v11 = (__high2float(h1) + by[nt] > 1.0f) ? 1.0f : 0.0f;
                *(float2*)(Cf + (size_t)r0 * Ntot + c) = make_float2(v00, v01);
                *(float2*)(Cf + (size_t)r1 * Ntot + c) = make_float2(v10, v11);
                if (WRITE_AUX) {
                    *(uint16_t*)(C8 + (size_t)r0 * Ntot + c) =
                        (uint16_t)((v00 != 0.0f ? FP8_ONE : 0u) |
                                   (v01 != 0.0f ? FP8_ONE << 8 : 0u));
                    *(uint16_t*)(C8 + (size_t)r1 * Ntot + c) =
                        (uint16_t)((v10 != 0.0f ? FP8_ONE : 0u) |
                                   (v11 != 0.0f ? FP8_ONE << 8 : 0u));
                    *(uint32_t*)(Cbf + (size_t)r0 * Ntot + c) =
                        (v00 != 0.0f ? BF16_ONE : 0u) |
                        (v01 != 0.0f ? BF16_ONE << 16 : 0u);
                    *(uint32_t*)(Cbf + (size_t)r1 * Ntot + c) =
                        (v10 != 0.0f ? BF16_ONE : 0u) |
                        (v11 != 0.0f ? BF16_ONE << 16 : 0u);
                }
            }
        }
    }
}

// ---------------------------------------------------------------------------
// Classifier via bf16 mma with exact W split (proven in R8):
//   C[b][l] = sum_h zbf[b][h] * (Whi[l][h] + Wlo[l][h])
// ---------------------------------------------------------------------------
#define LDT 80
#define CLF_T (128 * LDT)          // 10240 per tile
#define CLF_STG (3 * CLF_T)        // 30720 per stage (A, Whi, Wlo)
#define CLF_SMEM (3 * CLF_STG)     // 92160

__global__ __launch_bounds__(256) void clf_mma_kernel(
    const uint16_t* __restrict__ Z, const uint16_t* __restrict__ Whi,
    const uint16_t* __restrict__ Wlo, float* __restrict__ C) {
    constexpr int NCH = HV / 32;
    extern __shared__ __align__(16) uint8_t smem[];
    const uint32_t s0 = smem_u32(smem);

    const int tid  = threadIdx.x;
    const int lane = tid & 31;
    const int wid  = tid >> 5;
    const int wm   = wid & 3;
    const int wn   = wid >> 2;
    const int m0   = blockIdx.x * 128;

    const int gr = tid >> 2;
    const int gq = (tid & 3) * 16;
    const uint8_t* gA = (const uint8_t*)Z + ((size_t)(m0 + gr) * HV) * 2 + gq;
    const uint8_t* gH = (const uint8_t*)Whi + ((size_t)gr * HV) * 2 + gq;
    const uint8_t* gL = (const uint8_t*)Wlo + ((size_t)gr * HV) * 2 + gq;
    const uint32_t wA = s0 + gr * LDT + gq;
    const uint32_t wH = wA + CLF_T;
    const uint32_t wL = wH + CLF_T;

    const int a_row = wm * 32 + (lane & 7) + ((lane >> 3) & 1) * 8;
    const int a_qc  = (lane >> 4);
    const int b_row = wn * 64 + (lane & 7) + ((lane >> 4) & 1) * 8;
    const int b_qc  = (lane >> 3) & 1;
    const uint32_t rdA0 = s0 + a_row * LDT + a_qc * 16;
    const uint32_t rdH0 = s0 + CLF_T + b_row * LDT + b_qc * 16;
    const uint32_t rdL0 = rdH0 + CLF_T;

    float acc[2][8][4];
#pragma unroll
    for (int mt = 0; mt < 2; mt++)
#pragma unroll
        for (int nt = 0; nt < 8; nt++)
#pragma unroll
            for (int c = 0; c < 4; c++) acc[mt][nt][c] = 0.0f;

    auto issue = [&](int ch, int st) {
        const uint32_t off = st * CLF_STG;
        const int kc = ch * 64;
        cp16(wA + off, gA + kc);
        cp16(wA + off + 64 * LDT, gA + (size_t)64 * HV * 2 + kc);
        cp16(wH + off, gH + kc);
        cp16(wH + off + 64 * LDT, gH + (size_t)64 * HV * 2 + kc);
        cp16(wL + off, gL + kc);
        cp16(wL + off + 64 * LDT, gL + (size_t)64 * HV * 2 + kc);
        CP_COMMIT();
    };
    issue(0, 0);
    issue(1, 1);

    int st = 0, st_wr = 2;
    for (int ch = 0; ch < NCH; ch++) {
        if (ch + 1 < NCH) { CP_WAIT(1); } else { CP_WAIT(0); }
        __syncthreads();
        if (ch + 2 < NCH) {
            issue(ch + 2, st_wr);
            st_wr = (st_wr == 2) ? 0 : st_wr + 1;
        }
        const uint32_t rdA = rdA0 + st * CLF_STG;
        const uint32_t rdH = rdH0 + st * CLF_STG;
        const uint32_t rdL = rdL0 + st * CLF_STG;
#pragma unroll
        for (int ks = 0; ks < 2; ks++) {
            uint32_t af[2][4];
            ldm_x4(af[0], rdA + ks * 32);
            ldm_x4(af[1], rdA + 16 * LDT + ks * 32);
            uint32_t bh[8][2], bl[8][2];
#pragma unroll
            for (int nt2 = 0; nt2 < 4; nt2++) {
                uint32_t t[4];
                ldm_x4(t, rdH + nt2 * 16 * LDT + ks * 32);
                bh[2 * nt2][0] = t[0]; bh[2 * nt2][1] = t[1];
                bh[2 * nt2 + 1][0] = t[2]; bh[2 * nt2 + 1][1] = t[3];
                ldm_x4(t, rdL + nt2 * 16 * LDT + ks * 32);
                bl[2 * nt2][0] = t[0]; bl[2 * nt2][1] = t[1];
                bl[2 * nt2 + 1][0] = t[2]; bl[2 * nt2 + 1][1] = t[3];
            }
#pragma unroll
            for (int mt = 0; mt < 2; mt++)
#pragma unroll
                for (int nt = 0; nt < 8; nt++) {
                    mma_bf16(acc[mt][nt], af[mt], bh[nt][0], bh[nt][1]);
                    mma_bf16(acc[mt][nt], af[mt], bl[nt][0], bl[nt][1]);
                }
        }
        st = (st == 2) ? 0 : st + 1;
    }

    {
        const int g  = lane >> 2;
        const int tg = lane & 3;
        const int rbase = m0 + wm * 32 + g;
        const int cbase = wn * 64 + tg * 2;
#pragma unroll
        for (int mt = 0; mt < 2; mt++) {
            const int r0 = rbase + mt * 16;
            const int r1 = r0 + 8;
#pragma unroll
            for (int nt = 0; nt < 8; nt++) {
                const int c = cbase + nt * 8;
                *(float2*)(C + (size_t)r0 * LV + c) =
                    make_float2(acc[mt][nt][0], acc[mt][nt][1]);
                *(float2*)(C + (size_t)r1 * LV + c) =
                    make_float2(acc[mt][nt][2], acc[mt][nt][3]);
            }
        }
    }
}

// ---------------------------------------------------------------------------
// Launch.  Output layout: [output (B*D) | classification (B*L) | z (B*H)].
// ---------------------------------------------------------------------------
extern "C" void kernel_launch(void* const* d_in, const int* in_sizes, int n_in,
                              void* d_out, int out_size) {
    const float* x     = (const float*)d_in[0];
    const float* w     = (const float*)d_in[1];
    const float* bias0 = (const float*)d_in[2];
    const float* bias3 = (const float*)d_in[3];
    const float* clf   = (const float*)d_in[4];

    float* out        = (float*)d_out;
    float* out_output = out;
    float* out_class  = out + (size_t)BV * DV;
    float* out_z      = out + (size_t)BV * DV + (size_t)BV * LV;

    uint8_t *x8, *w8, *wT8, *z8;
    uint16_t *zbf, *whi, *wlo;
    cudaGetSymbolAddress((void**)&x8, g_x8);
    cudaGetSymbolAddress((void**)&w8, g_w8);
    cudaGetSymbolAddress((void**)&wT8, g_wT8);
    cudaGetSymbolAddress((void**)&z8, g_z8);
    cudaGetSymbolAddress((void**)&zbf, g_zbf);
    cudaGetSymbolAddress((void**)&whi, g_whi);
    cudaGetSymbolAddress((void**)&wlo, g_wlo);

    cudaFuncSetAttribute(fp8_mma_gemm_kernel<DV, true>,
                         cudaFuncAttributeMaxDynamicSharedMemorySize, GEMM_SMEM);
    cudaFuncSetAttribute(fp8_mma_gemm_kernel<HV, false>,
                         cudaFuncAttributeMaxDynamicSharedMemorySize, GEMM_SMEM);
    cudaFuncSetAttribute(clf_mma_kernel,
                         cudaFuncAttributeMaxDynamicSharedMemorySize, CLF_SMEM);

    // 1) conversions
    cvt_fp8_kernel<<<(BV * DV / 4) / 256, 256>>>(x, (uint32_t*)x8, BV * DV / 4);
    cvt_w_both_kernel<<<dim3(DV / 256, HV / 32), 256>>>(w, w8, wT8);
    cvt_wsplit_kernel<<<(LV * HV) / 256, 256>>>(clf, whi, wlo, LV * HV);

    // 2) GEMM1: z = (x @ wb^T + bias0 > 1); emits float + e4m3 + bf16 copies
    fp8_mma_gemm_kernel<DV, true>
        <<<dim3(HV / 256, BV / 128), 256, GEMM_SMEM>>>(x8, w8, bias0, out_z, z8,
                                                       zbf, HV);

    // 3) GEMM2: output = (z @ wb + bias3 > 1)
    fp8_mma_gemm_kernel<HV, false>
        <<<dim3(DV / 256, BV / 128), 256, GEMM_SMEM>>>(z8, wT8, bias3, out_output,
                                                       nullptr, nullptr, DV);

    // 4) classification = z @ clf^T  (bf16 split, fp32 accum)
    clf_mma_kernel<<<BV / 128, 256, CLF_SMEM>>>(zbf, whi, wlo, out_class);
}

// round 12
// speedup vs baseline: 1.2367x; 1.2367x over previous
#include <cuda_runtime.h>
#include <cuda_bf16.h>
#include <cuda_fp16.h>
#include <cstdint>

// Problem constants (DiffnapsNet_42030549959310)
#define BV 4096   // batch
#define DV 8192   // data dim
#define HV 4096   // hidden
#define LV 128    // labels

#define FP8_ONE 0x38u     // e4m3 1.0
#define HW (HV / 32)      // zmask words per row = 128

// ---------------------------------------------------------------------------
// Scratch (device globals; no allocation allowed)
// ---------------------------------------------------------------------------
__device__ __align__(16) uint8_t  g_x8[(size_t)BV * DV];    // [B][D] e4m3
__device__ __align__(16) uint8_t  g_w8[(size_t)HV * DV];    // [H][D] e4m3
__device__ __align__(16) int      g_colsum[DV];             // sum_h wb[h][d]
__device__ __align__(16) uint32_t g_zmask[(size_t)BV * HW]; // bit=1 where z==0
__device__ __align__(16) double   g_rowsum[LV];             // sum_h clf[l][h]
__device__ __align__(16) float    g_basef[DV];              // thresholded base row

// ---------------------------------------------------------------------------
// PTX helpers (family-compatible: sm_80/89 features only)
// ---------------------------------------------------------------------------
__device__ __forceinline__ uint32_t smem_u32(const void* p) {
    uint32_t a;
    asm("{ .reg .u64 t; cvta.to.shared.u64 t, %1; cvt.u32.u64 %0, t; }"
        : "=r"(a) : "l"(p));
    return a;
}
__device__ __forceinline__ void cp16(uint32_t dst, const void* src) {
    asm volatile("cp.async.cg.shared.global [%0], [%1], 16;"
                 :: "r"(dst), "l"(src) : "memory");
}
#define CP_COMMIT() asm volatile("cp.async.commit_group;" ::: "memory")
#define CP_WAIT(n)  asm volatile("cp.async.wait_group %0;" :: "n"(n) : "memory")

__device__ __forceinline__ void ldm_x4(uint32_t (&r)[4], uint32_t addr) {
    asm volatile("ldmatrix.sync.aligned.m8n8.x4.shared.b16 {%0,%1,%2,%3}, [%4];"
                 : "=r"(r[0]), "=r"(r[1]), "=r"(r[2]), "=r"(r[3]) : "r"(addr));
}
// fp8 x fp8 -> fp16 accumulator: exact for integer counts (partials <= 2048
// whenever the result is near the threshold; larger counts can't flip it).
__device__ __forceinline__ void mma_fp8_h(uint32_t (&c)[2], const uint32_t (&a)[4],
                                          uint32_t b0, uint32_t b1) {
    asm volatile(
        "mma.sync.aligned.m16n8k32.row.col.f16.e4m3.e4m3.f16 "
        "{%0,%1}, {%2,%3,%4,%5}, {%6,%7}, {%0,%1};"
        : "+r"(c[0]), "+r"(c[1])
        : "r"(a[0]), "r"(a[1]), "r"(a[2]), "r"(a[3]), "r"(b0), "r"(b1));
}

// ---------------------------------------------------------------------------
// Conversions
// ---------------------------------------------------------------------------
__global__ void cvt_fp8_kernel(const float* __restrict__ src,
                               uint32_t* __restrict__ dst, int n4) {
    int i = blockIdx.x * blockDim.x + threadIdx.x;
    if (i < n4) {
        float4 v = ((const float4*)src)[i];
        uint32_t w = (v.x > 0.5f ? FP8_ONE : 0u) | (v.y > 0.5f ? FP8_ONE << 8 : 0u) |
                     (v.z > 0.5f ? FP8_ONE << 16 : 0u) | (v.w > 0.5f ? FP8_ONE << 24 : 0u);
        dst[i] = w;
    }
}

// enc_weight -> w8 (e4m3 row-major) + column-sum partials (exact ints).
__global__ void cvt_w_colsum_kernel(const float* __restrict__ w,
                                    uint8_t* __restrict__ w8,
                                    int* __restrict__ colsum) {
    int d  = blockIdx.x * blockDim.x + threadIdx.x;  // 0..DV-1
    int hw = blockIdx.y;                             // 0..HV/32-1
    const float* col = w + (size_t)hw * 32 * DV + d;
    int part = 0;
#pragma unroll
    for (int i = 0; i < 32; i++) {
        bool b = col[(size_t)i * DV] > 0.5f;
        w8[(size_t)(hw * 32 + i) * DV + d] = b ? (uint8_t)FP8_ONE : 0;
        part += b;
    }
    atomicAdd(&colsum[d], part);
}

// Row sums of clf (double, fixed-order tree reduction -> deterministic).
__global__ void clf_rowsum_kernel(const float* __restrict__ clf,
                                  double* __restrict__ rowsum) {
    __shared__ double sm[256];
    const int l = blockIdx.x;
    const int t = threadIdx.x;
    double p = 0.0;
    for (int k = t; k < HV; k += 256) p += (double)clf[(size_t)l * HV + k];
    sm[t] = p;
    __syncthreads();
    for (int s = 128; s > 0; s >>= 1) {
        if (t < s) sm[t] += sm[t + s];
        __syncthreads();
    }
    if (t == 0) rowsum[l] = sm[0];
}

// Thresholded base reconstruction row: basef[d] = (colsum[d]+bias3[d] > 1).
__global__ void base_row_kernel(const int* __restrict__ colsum,
                                const float* __restrict__ bias3,
                                float* __restrict__ basef) {
    int d = blockIdx.x * blockDim.x + threadIdx.x;
    if (d < DV)
        basef[d] = ((float)colsum[d] + bias3[d] > 1.0f) ? 1.0f : 0.0f;
}

// ---------------------------------------------------------------------------
// GEMM1: FP8 mma.sync, fp16 accumulators (R11 config: CTA 128x256, 8 warps
// 2x4, warp tile 64x64, 128B K-chunks, 2-stage double buffer, stride 144B).
// Epilogue: z = (cnt + bias0 > 1) -> float out; zeros recorded in g_zmask.
// ---------------------------------------------------------------------------
#define KLDT 144
#define KATILE (128 * KLDT)          // 18432
#define KBTILE (256 * KLDT)          // 36864
#define KSTAGE (KATILE + KBTILE)     // 55296
#define GEMM_SMEM (2 * KSTAGE)       // 110592

__global__ __launch_bounds__(256, 2) void fp8_mma_gemm1_kernel(
    const uint8_t* __restrict__ A, const uint8_t* __restrict__ Bm,
    const float* __restrict__ bias, float* __restrict__ Cf,
    uint32_t* __restrict__ zmask) {
    constexpr int KB = DV;
    constexpr int NCH = KB / 128;
    extern __shared__ __align__(16) uint8_t smem[];
    const uint32_t s0 = smem_u32(smem);

    const int tid  = threadIdx.x;
    const int lane = tid & 31;
    const int wid  = tid >> 5;
    const int wm   = wid >> 2;   // 0..1 : m offset wm*64
    const int wn   = wid & 3;    // 0..3 : n offset wn*64
    const int m0   = blockIdx.y * 128;
    const int n0   = blockIdx.x * 256;

    const int crow = tid >> 3;
    const int cq   = (tid & 7) * 16;
    const uint8_t* gA = A + (size_t)(m0 + crow) * KB + cq;
    const uint8_t* gB = Bm + (size_t)(n0 + crow) * KB + cq;
    const uint32_t wAo = crow * KLDT + cq;
    const uint32_t wBo = KATILE + crow * KLDT + cq;

    const uint32_t rdA0 = s0 +
        (wm * 64 + (lane & 7) + ((lane >> 3) & 1) * 8) * KLDT + (lane >> 4) * 16;
    const uint32_t rdB0 = s0 + KATILE +
        (wn * 64 + (lane & 7) + ((lane >> 4) & 1) * 8) * KLDT + ((lane >> 3) & 1) * 16;

    uint32_t acc[4][8][2];
#pragma unroll
    for (int mt = 0; mt < 4; mt++)
#pragma unroll
        for (int nt = 0; nt < 8; nt++) { acc[mt][nt][0] = 0u; acc[mt][nt][1] = 0u; }

    auto issue = [&](int ch, int st) {
        const uint32_t base = s0 + (uint32_t)st * KSTAGE;
        const int kc = ch * 128;
#pragma unroll
        for (int p = 0; p < 4; p++)
            cp16(base + wAo + p * 32 * KLDT, gA + (size_t)(p * 32) * KB + kc);
#pragma unroll
        for (int p = 0; p < 8; p++)
            cp16(base + wBo + p * 32 * KLDT, gB + (size_t)(p * 32) * KB + kc);
        CP_COMMIT();
    };
    issue(0, 0);

    for (int ch = 0; ch < NCH; ch++) {
        CP_WAIT(0);
        __syncthreads();
        if (ch + 1 < NCH) issue(ch + 1, (ch + 1) & 1);

        const uint32_t off = (uint32_t)(ch & 1) * KSTAGE;
#pragma unroll
        for (int ks = 0; ks < 4; ks++) {
            uint32_t bf[8][2];
#pragma unroll
            for (int nt2 = 0; nt2 < 4; nt2++) {
                uint32_t t[4];
                ldm_x4(t, rdB0 + off + nt2 * 16 * KLDT + ks * 32);
                bf[2 * nt2][0] = t[0]; bf[2 * nt2][1] = t[1];
                bf[2 * nt2 + 1][0] = t[2]; bf[2 * nt2 + 1][1] = t[3];
            }
#pragma unroll
            for (int mt = 0; mt < 4; mt++) {
                uint32_t af[4];
                ldm_x4(af, rdA0 + off + mt * 16 * KLDT + ks * 32);
#pragma unroll
                for (int nt = 0; nt < 8; nt++)
                    mma_fp8_h(acc[mt][nt], af, bf[nt][0], bf[nt][1]);
            }
        }
    }

    // epilogue: threshold; record zeros (rare) in zmask via atomicOr.
    {
        const int g  = lane >> 2;
        const int tg = lane & 3;
        const int cbase = n0 + wn * 64 + tg * 2;
        float bx[8], by[8];
#pragma unroll
        for (int nt = 0; nt < 8; nt++) {
            bx[nt] = bias[cbase + nt * 8];
            by[nt] = bias[cbase + nt * 8 + 1];
        }
#pragma unroll
        for (int mt = 0; mt < 4; mt++) {
            const int r0 = m0 + wm * 64 + mt * 16 + g;
            const int r1 = r0 + 8;
#pragma unroll
            for (int nt = 0; nt < 8; nt++) {
                const int c = cbase + nt * 8;
                __half2 h0 = *(__half2*)&acc[mt][nt][0];
                __half2 h1 = *(__half2*)&acc[mt][nt][1];
                float v00 = (__low2float(h0) + bx[nt] > 1.0f) ? 1.0f : 0.0f;
                float v01 = (__high2float(h0) + by[nt] > 1.0f) ? 1.0f : 0.0f;
                float v10 = (__low2float(h1) + bx[nt] > 1.0f) ? 1.0f : 0.0f;
                float v11 = (__high2float(h1) + by[nt] > 1.0f) ? 1.0f : 0.0f;
                *(float2*)(Cf + (size_t)r0 * HV + c) = make_float2(v00, v01);
                *(float2*)(Cf + (size_t)r1 * HV + c) = make_float2(v10, v11);
                if (v00 == 0.0f) atomicOr(&zmask[(size_t)r0 * HW + (c >> 5)], 1u << (c & 31));
                if (v01 == 0.0f) atomicOr(&zmask[(size_t)r0 * HW + ((c + 1) >> 5)], 1u << ((c + 1) & 31));
                if (v10 == 0.0f) atomicOr(&zmask[(size_t)r1 * HW + (c >> 5)], 1u << (c & 31));
                if (v11 == 0.0f) atomicOr(&zmask[(size_t)r1 * HW + ((c + 1) >> 5)], 1u << ((c + 1) & 31));
            }
        }
    }
}

// ---------------------------------------------------------------------------
// Output writer: out[b][d] = (colsum[d] - sum_{h in zeros_b} wb[h][d]
//                             + bias3[d] > 1)
// Clean rows (no zeros, overwhelmingly common) copy the precomputed base row.
// ---------------------------------------------------------------------------
__global__ __launch_bounds__(256) void recon_write_kernel(
    const uint32_t* __restrict__ zmask, const int* __restrict__ colsum,
    const float* __restrict__ basef, const float* __restrict__ bias3,
    const uint8_t* __restrict__ w8, float* __restrict__ out) {
    const int b = blockIdx.x;
    const int t = threadIdx.x;
    __shared__ uint32_t mrow[HW];
    __shared__ int any;
    if (t == 0) any = 0;
    __syncthreads();
    if (t < HW) {
        uint32_t m = zmask[(size_t)b * HW + t];
        mrow[t] = m;
        if (m) atomicOr(&any, 1);
    }
    __syncthreads();

    float* dst = out + (size_t)b * DV;
    if (!any) {
        // fast path: copy base row (float4)
        for (int d4 = t; d4 < DV / 4; d4 += 256)
            ((float4*)dst)[d4] = ((const float4*)basef)[d4];
        return;
    }
    // slow path: recompute counts for this row (exact integers).
    int cnt[DV / 256];
#pragma unroll
    for (int i = 0; i < DV / 256; i++) cnt[i] = colsum[t + i * 256];
    for (int wq = 0; wq < HW; wq++) {
        uint32_t m = mrow[wq];
        while (m) {
            int bit = __ffs(m) - 1;
            m &= m - 1;
            const uint8_t* wrow = w8 + (size_t)(wq * 32 + bit) * DV;
#pragma unroll
            for (int i = 0; i < DV / 256; i++)
                cnt[i] -= (wrow[t + i * 256] != 0);
        }
    }
#pragma unroll
    for (int i = 0; i < DV / 256; i++) {
        int d = t + i * 256;
        dst[d] = ((float)cnt[i] + bias3[d] > 1.0f) ? 1.0f : 0.0f;
    }
}

// ---------------------------------------------------------------------------
// Classifier: class[b][l] = rowsum[l] - sum_{h in zeros_b} clf[l][h]
// (double accumulation, deterministic scan order).
// ---------------------------------------------------------------------------
__global__ __launch_bounds__(128) void clf_write_kernel(
    const uint32_t* __restrict__ zmask, const double* __restrict__ rowsum,
    const float* __restrict__ clf, float* __restrict__ out) {
    const int b = blockIdx.x;
    const int l = threadIdx.x;  // 0..127
    __shared__ uint32_t mrow[HW];
    mrow[l] = zmask[(size_t)b * HW + l];
    __syncthreads();

    double corr = 0.0;
    for (int wq = 0; wq < HW; wq++) {
        uint32_t m = mrow[wq];
        while (m) {
            int bit = __ffs(m) - 1;
            m &= m - 1;
            corr += (double)clf[(size_t)l * HV + wq * 32 + bit];
        }
    }
    out[(size_t)b * LV + l] = (float)(rowsum[l] - corr);
}

// ---------------------------------------------------------------------------
// Launch.  Output layout: [output (B*D) | classification (B*L) | z (B*H)].
// ---------------------------------------------------------------------------
extern "C" void kernel_launch(void* const* d_in, const int* in_sizes, int n_in,
                              void* d_out, int out_size) {
    const float* x     = (const float*)d_in[0];
    const float* w     = (const float*)d_in[1];
    const float* bias0 = (const float*)d_in[2];
    const float* bias3 = (const float*)d_in[3];
    const float* clf   = (const float*)d_in[4];

    float* out        = (float*)d_out;
    float* out_output = out;
    float* out_class  = out + (size_t)BV * DV;
    float* out_z      = out + (size_t)BV * DV + (size_t)BV * LV;

    uint8_t *x8, *w8;
    int* colsum;
    uint32_t* zmask;
    double* rowsum;
    float* basef;
    cudaGetSymbolAddress((void**)&x8, g_x8);
    cudaGetSymbolAddress((void**)&w8, g_w8);
    cudaGetSymbolAddress((void**)&colsum, g_colsum);
    cudaGetSymbolAddress((void**)&zmask, g_zmask);
    cudaGetSymbolAddress((void**)&rowsum, g_rowsum);
    cudaGetSymbolAddress((void**)&basef, g_basef);

    cudaFuncSetAttribute(fp8_mma_gemm1_kernel,
                         cudaFuncAttributeMaxDynamicSharedMemorySize, GEMM_SMEM);

    // 0) zero accumulators (persistent globals -> must reset every call)
    cudaMemsetAsync(colsum, 0, DV * sizeof(int));
    cudaMemsetAsync(zmask, 0, (size_t)BV * HW * sizeof(uint32_t));

    // 1) conversions + precomputed sums
    cvt_fp8_kernel<<<(BV * DV / 4) / 256, 256>>>(x, (uint32_t*)x8, BV * DV / 4);
    cvt_w_colsum_kernel<<<dim3(DV / 256, HV / 32), 256>>>(w, w8, colsum);
    clf_rowsum_kernel<<<LV, 256>>>(clf, rowsum);
    base_row_kernel<<<DV / 256, 256>>>(colsum, bias3, basef);

    // 2) GEMM1: z = (x @ wb^T + bias0 > 1); zeros recorded in zmask
    fp8_mma_gemm1_kernel
        <<<dim3(HV / 256, BV / 128), 256, GEMM_SMEM>>>(x8, w8, bias0, out_z, zmask);

    // 3) output = (colsum - corrections + bias3 > 1)   [exact, integer]
    recon_write_kernel<<<BV, 256>>>(zmask, colsum, basef, bias3, w8, out_output);

    // 4) classification = rowsum - corrections          [double, deterministic]
    clf_write_kernel<<<BV, 128>>>(zmask, rowsum, clf, out_class);
}

// round 13
// speedup vs baseline: 4.6899x; 3.7922x over previous
#include <cuda_runtime.h>
#include <cstdint>

// Problem constants (DiffnapsNet_42030549959310)
#define BV 4096   // batch
#define DV 8192   // data dim
#define HV 4096   // hidden
#define LV 128    // labels

#define HW (HV / 32)      // 128  : zmask / wT words per h-row
#define DW (DV / 32)      // 256  : w_bits words per d-row

// ---------------------------------------------------------------------------
// Scratch (device globals; no allocation allowed)
// ---------------------------------------------------------------------------
__device__ __align__(16) uint32_t g_wT_bits[(size_t)DV * HW];  // [D][H/32] bits
__device__ __align__(16) uint32_t g_w_bits[(size_t)HV * DW];   // [H][D/32] bits
__device__ __align__(16) uint16_t g_xidx[(size_t)BV * DV];     // active-d lists
__device__ __align__(16) int      g_xcnt[BV];
__device__ __align__(16) int      g_colsum[DV];                // sum_h wb[h][d]
__device__ __align__(16) uint32_t g_zmask[(size_t)BV * HW];    // bit=1 where z==0
__device__ __align__(16) double   g_rowsum[LV];                // sum_h clf[l][h]
__device__ __align__(16) float    g_basef[DV];                 // thresholded base row

// ---------------------------------------------------------------------------
// Pack enc_weight into bits (both layouts) + column sums.
// Thread (d, hy): column d, h-group hy*32..+31.
//   wT_bits[d][hy]           : bit i = wb[hy*32+i][d]
//   w_bits[hy*32+i][d>>5]    : bit (d&31) = wb[hy*32+i][d]  (via warp ballot)
// ---------------------------------------------------------------------------
__global__ void pack_w_kernel(const float* __restrict__ w,
                              uint32_t* __restrict__ wT,
                              uint32_t* __restrict__ wb,
                              int* __restrict__ colsum) {
    const int d    = blockIdx.x * blockDim.x + threadIdx.x;  // 0..DV-1
    const int hy   = blockIdx.y;                             // 0..HV/32-1
    const int lane = threadIdx.x & 31;
    const float* col = w + (size_t)hy * 32 * DV + d;

    uint32_t v = 0;
    uint32_t mymask = 0;
#pragma unroll
    for (int i = 0; i < 32; i++) {
        bool b = col[(size_t)i * DV] > 0.5f;
        if (b) v |= 1u << i;
        uint32_t m = __ballot_sync(0xffffffffu, b);
        if (lane == i) mymask = m;
    }
    wT[(size_t)d * HW + hy] = v;
    const int dw = d >> 5;  // same for whole warp
    wb[(size_t)(hy * 32 + lane) * DW + dw] = mymask;
    atomicAdd(&colsum[d], __popc(v));
}

// Row sums of clf (double, fixed-order tree reduction -> deterministic).
__global__ void clf_rowsum_kernel(const float* __restrict__ clf,
                                  double* __restrict__ rowsum) {
    __shared__ double sm[256];
    const int l = blockIdx.x;
    const int t = threadIdx.x;
    double p = 0.0;
    for (int k = t; k < HV; k += 256) p += (double)clf[(size_t)l * HV + k];
    sm[t] = p;
    __syncthreads();
    for (int s = 128; s > 0; s >>= 1) {
        if (t < s) sm[t] += sm[t + s];
        __syncthreads();
    }
    if (t == 0) rowsum[l] = sm[0];
}

// Thresholded base reconstruction row: basef[d] = (colsum[d]+bias3[d] > 1).
__global__ void base_row_kernel(const int* __restrict__ colsum,
                                const float* __restrict__ bias3,
                                float* __restrict__ basef) {
    int d = blockIdx.x * blockDim.x + threadIdx.x;
    if (d < DV)
        basef[d] = ((float)colsum[d] + bias3[d] > 1.0f) ? 1.0f : 0.0f;
}

// ---------------------------------------------------------------------------
// Compact x row -> list of active d indices (order-independent).
// ---------------------------------------------------------------------------
__global__ __launch_bounds__(256) void compact_x_kernel(
    const float* __restrict__ x, uint16_t* __restrict__ xidx,
    int* __restrict__ xcnt) {
    const int b = blockIdx.x;
    const int t = threadIdx.x;
    __shared__ int cnt;
    if (t == 0) cnt = 0;
    __syncthreads();
    const float4* row = (const float4*)(x + (size_t)b * DV);
    uint16_t* dst = xidx + (size_t)b * DV;
#pragma unroll
    for (int q = 0; q < DV / 4 / 256; q++) {
        int i4 = t + q * 256;
        float4 v = row[i4];
        if (v.x > 0.5f) dst[atomicAdd(&cnt, 1)] = (uint16_t)(i4 * 4);
        if (v.y > 0.5f) dst[atomicAdd(&cnt, 1)] = (uint16_t)(i4 * 4 + 1);
        if (v.z > 0.5f) dst[atomicAdd(&cnt, 1)] = (uint16_t)(i4 * 4 + 2);
        if (v.w > 0.5f) dst[atomicAdd(&cnt, 1)] = (uint16_t)(i4 * 4 + 3);
    }
    __syncthreads();
    if (t == 0) xcnt[b] = cnt;
}

// ---------------------------------------------------------------------------
// Sparse GEMM1 via 3-level saturating bit-counters.
// One CTA (128 threads) per batch row; thread t owns h-word t (h = t*32..+31).
// For each active d: bits = wT[d][t]; s3|=s2&bits; s2|=s1&bits; s1|=bits.
// min(cnt,3) per h is exact; z = ((float)min(cnt,3) + bias0 > 1) is the
// reference decision bit-exactly (fp32 add monotone; bias0 > -2).
// ---------------------------------------------------------------------------
__global__ __launch_bounds__(128) void sparse_gemm1_kernel(
    const uint16_t* __restrict__ xidx, const int* __restrict__ xcnt,
    const uint32_t* __restrict__ wT, const float* __restrict__ bias0,
    float* __restrict__ Zf, uint32_t* __restrict__ zmask) {
    const int b = blockIdx.x;
    const int t = threadIdx.x;  // 0..127
    __shared__ uint16_t sidx[512];

    const int n = xcnt[b];
    const uint16_t* idx = xidx + (size_t)b * DV;
    uint32_t s1 = 0, s2 = 0, s3 = 0;

    for (int base = 0; base < n; base += 512) {
        const int m = min(512, n - base);
        __syncthreads();
        for (int j = t; j < m; j += 128) sidx[j] = idx[base + j];
        __syncthreads();
        int j = 0;
        for (; j + 8 <= m; j += 8) {
            uint32_t w0 = wT[(size_t)sidx[j + 0] * HW + t];
            uint32_t w1 = wT[(size_t)sidx[j + 1] * HW + t];
            uint32_t w2 = wT[(size_t)sidx[j + 2] * HW + t];
            uint32_t w3 = wT[(size_t)sidx[j + 3] * HW + t];
            uint32_t w4 = wT[(size_t)sidx[j + 4] * HW + t];
            uint32_t w5 = wT[(size_t)sidx[j + 5] * HW + t];
            uint32_t w6 = wT[(size_t)sidx[j + 6] * HW + t];
            uint32_t w7 = wT[(size_t)sidx[j + 7] * HW + t];
            s3 |= s2 & w0; s2 |= s1 & w0; s1 |= w0;
            s3 |= s2 & w1; s2 |= s1 & w1; s1 |= w1;
            s3 |= s2 & w2; s2 |= s1 & w2; s1 |= w2;
            s3 |= s2 & w3; s2 |= s1 & w3; s1 |= w3;
            s3 |= s2 & w4; s2 |= s1 & w4; s1 |= w4;
            s3 |= s2 & w5; s2 |= s1 & w5; s1 |= w5;
            s3 |= s2 & w6; s2 |= s1 & w6; s1 |= w6;
            s3 |= s2 & w7; s2 |= s1 & w7; s1 |= w7;
        }
        for (; j < m; j++) {
            uint32_t wv = wT[(size_t)sidx[j] * HW + t];
            s3 |= s2 & wv; s2 |= s1 & wv; s1 |= wv;
        }
    }

    // epilogue: z floats + zmask word (full overwrite -> no memset needed)
    const float* bs = bias0 + t * 32;
    float* dst = Zf + (size_t)b * HV + t * 32;
    uint32_t zm = 0;
#pragma unroll
    for (int q = 0; q < 8; q++) {
        float4 v;
        float* vp = (float*)&v;
#pragma unroll
        for (int c = 0; c < 4; c++) {
            const int bit = q * 4 + c;
            int sat = ((s1 >> bit) & 1) + ((s2 >> bit) & 1) + ((s3 >> bit) & 1);
            float z = ((float)sat + bs[bit] > 1.0f) ? 1.0f : 0.0f;
            vp[c] = z;
            if (z == 0.0f) zm |= 1u << bit;
        }
        *(float4*)(dst + q * 4) = v;
    }
    zmask[(size_t)b * HW + t] = zm;
}

// ---------------------------------------------------------------------------
// Output writer: out[b][d] = (colsum[d] - sum_{h in zeros_b} wb[h][d]
//                             + bias3[d] > 1)
// Clean rows (no zeros; overwhelmingly common) copy the precomputed base row.
// ---------------------------------------------------------------------------
__global__ __launch_bounds__(256) void recon_write_kernel(
    const uint32_t* __restrict__ zmask, const int* __restrict__ colsum,
    const float* __restrict__ basef, const float* __restrict__ bias3,
    const uint32_t* __restrict__ wb, float* __restrict__ out) {
    const int b = blockIdx.x;
    const int t = threadIdx.x;
    __shared__ uint32_t mrow[HW];
    __shared__ int any;
    if (t == 0) any = 0;
    __syncthreads();
    if (t < HW) {
        uint32_t m = zmask[(size_t)b * HW + t];
        mrow[t] = m;
        if (m) atomicOr(&any, 1);
    }
    __syncthreads();

    float* dst = out + (size_t)b * DV;
    if (!any) {
        for (int d4 = t; d4 < DV / 4; d4 += 256)
            ((float4*)dst)[d4] = ((const float4*)basef)[d4];
        return;
    }
    // slow path: exact integer correction using bit-packed wb rows.
    int cnt[DV / 256];
#pragma unroll
    for (int i = 0; i < DV / 256; i++) cnt[i] = colsum[t + i * 256];
    for (int wq = 0; wq < HW; wq++) {
        uint32_t m = mrow[wq];
        while (m) {
            int bit = __ffs(m) - 1;
            m &= m - 1;
            const uint32_t* wrow = wb + (size_t)(wq * 32 + bit) * DW;
#pragma unroll
            for (int i = 0; i < DV / 256; i++) {
                int d = t + i * 256;
                cnt[i] -= (wrow[d >> 5] >> (d & 31)) & 1;
            }
        }
    }
#pragma unroll
    for (int i = 0; i < DV / 256; i++) {
        int d = t + i * 256;
        dst[d] = ((float)cnt[i] + bias3[d] > 1.0f) ? 1.0f : 0.0f;
    }
}

// ---------------------------------------------------------------------------
// Classifier: class[b][l] = rowsum[l] - sum_{h in zeros_b} clf[l][h]
// (double accumulation, deterministic scan order).
// ---------------------------------------------------------------------------
__global__ __launch_bounds__(128) void clf_write_kernel(
    const uint32_t* __restrict__ zmask, const double* __restrict__ rowsum,
    const float* __restrict__ clf, float* __restrict__ out) {
    const int b = blockIdx.x;
    const int l = threadIdx.x;  // 0..127
    __shared__ uint32_t mrow[HW];
    mrow[l] = zmask[(size_t)b * HW + l];
    __syncthreads();

    double corr = 0.0;
    for (int wq = 0; wq < HW; wq++) {
        uint32_t m = mrow[wq];
        while (m) {
            int bit = __ffs(m) - 1;
            m &= m - 1;
            corr += (double)clf[(size_t)l * HV + wq * 32 + bit];
        }
    }
    out[(size_t)b * LV + l] = (float)(rowsum[l] - corr);
}

// ---------------------------------------------------------------------------
// Launch.  Output layout: [output (B*D) | classification (B*L) | z (B*H)].
// ---------------------------------------------------------------------------
extern "C" void kernel_launch(void* const* d_in, const int* in_sizes, int n_in,
                              void* d_out, int out_size) {
    const float* x     = (const float*)d_in[0];
    const float* w     = (const float*)d_in[1];
    const float* bias0 = (const float*)d_in[2];
    const float* bias3 = (const float*)d_in[3];
    const float* clf   = (const float*)d_in[4];

    float* out        = (float*)d_out;
    float* out_output = out;
    float* out_class  = out + (size_t)BV * DV;
    float* out_z      = out + (size_t)BV * DV + (size_t)BV * LV;

    uint32_t *wT, *wb, *zmask;
    uint16_t* xidx;
    int *xcnt, *colsum;
    double* rowsum;
    float* basef;
    cudaGetSymbolAddress((void**)&wT, g_wT_bits);
    cudaGetSymbolAddress((void**)&wb, g_w_bits);
    cudaGetSymbolAddress((void**)&xidx, g_xidx);
    cudaGetSymbolAddress((void**)&xcnt, g_xcnt);
    cudaGetSymbolAddress((void**)&colsum, g_colsum);
    cudaGetSymbolAddress((void**)&zmask, g_zmask);
    cudaGetSymbolAddress((void**)&rowsum, g_rowsum);
    cudaGetSymbolAddress((void**)&basef, g_basef);

    // 0) zero the one accumulator that needs it
    cudaMemsetAsync(colsum, 0, DV * sizeof(int));

    // 1) pack weights (both layouts) + colsum; clf row sums; x compaction
    pack_w_kernel<<<dim3(DV / 256, HV / 32), 256>>>(w, wT, wb, colsum);
    clf_rowsum_kernel<<<LV, 256>>>(clf, rowsum);
    compact_x_kernel<<<BV, 256>>>(x, xidx, xcnt);
    base_row_kernel<<<DV / 256, 256>>>(colsum, bias3, basef);

    // 2) sparse GEMM1: z + zmask via saturating bit-counters (exact)
    sparse_gemm1_kernel<<<BV, 128>>>(xidx, xcnt, wT, bias0, out_z, zmask);

    // 3) output = (colsum - corrections + bias3 > 1)   [exact, integer]
    recon_write_kernel<<<BV, 256>>>(zmask, colsum, basef, bias3, wb, out_output);

    // 4) classification = rowsum - corrections          [double, deterministic]
    clf_write_kernel<<<BV, 128>>>(zmask, rowsum, clf, out_class);
}

// round 14
// speedup vs baseline: 7.7188x; 1.6458x over previous
#include <cuda_runtime.h>
#include <cstdint>

// Problem constants (DiffnapsNet_42030549959310)
#define BV 4096   // batch
#define DV 8192   // data dim
#define HV 4096   // hidden
#define LV 128    // labels

#define HW (HV / 32)      // 128  : zmask / wT words per h-row
#define DW (DV / 32)      // 256  : w_bits words per d-row

// ---------------------------------------------------------------------------
// Scratch (device globals; no allocation allowed)
// ---------------------------------------------------------------------------
__device__ __align__(16) uint32_t g_wT_bits[(size_t)DV * HW];  // [D][H/32] bits
__device__ __align__(16) uint32_t g_w_bits[(size_t)HV * DW];   // [H][D/32] bits
__device__ __align__(16) uint16_t g_xidx[(size_t)BV * DV];     // active-d lists
__device__ __align__(16) int      g_xcnt[BV];
__device__ __align__(16) int      g_colsum[DV];                // sum_h wb[h][d]
__device__ __align__(16) uint32_t g_zmask[(size_t)BV * HW];    // bit=1 where z==0
__device__ __align__(16) double   g_rowsum[LV];                // sum_h clf[l][h]
__device__ __align__(16) float    g_basef[DV];                 // thresholded base row

// ---------------------------------------------------------------------------
// Pack enc_weight into bits (both layouts) + column sums.
// ---------------------------------------------------------------------------
__global__ void pack_w_kernel(const float* __restrict__ w,
                              uint32_t* __restrict__ wT,
                              uint32_t* __restrict__ wb,
                              int* __restrict__ colsum) {
    const int d    = blockIdx.x * blockDim.x + threadIdx.x;  // 0..DV-1
    const int hy   = blockIdx.y;                             // 0..HV/32-1
    const int lane = threadIdx.x & 31;
    const float* col = w + (size_t)hy * 32 * DV + d;

    uint32_t v = 0;
    uint32_t mymask = 0;
#pragma unroll
    for (int i = 0; i < 32; i++) {
        bool b = col[(size_t)i * DV] > 0.5f;
        if (b) v |= 1u << i;
        uint32_t m = __ballot_sync(0xffffffffu, b);
        if (lane == i) mymask = m;
    }
    wT[(size_t)d * HW + hy] = v;
    const int dw = d >> 5;
    wb[(size_t)(hy * 32 + lane) * DW + dw] = mymask;
    atomicAdd(&colsum[d], __popc(v));
}

// Row sums of clf (double, fixed-order tree reduction -> deterministic).
__global__ void clf_rowsum_kernel(const float* __restrict__ clf,
                                  double* __restrict__ rowsum) {
    __shared__ double sm[256];
    const int l = blockIdx.x;
    const int t = threadIdx.x;
    double p = 0.0;
    for (int k = t; k < HV; k += 256) p += (double)clf[(size_t)l * HV + k];
    sm[t] = p;
    __syncthreads();
    for (int s = 128; s > 0; s >>= 1) {
        if (t < s) sm[t] += sm[t + s];
        __syncthreads();
    }
    if (t == 0) rowsum[l] = sm[0];
}

// Thresholded base reconstruction row: basef[d] = (colsum[d]+bias3[d] > 1).
__global__ void base_row_kernel(const int* __restrict__ colsum,
                                const float* __restrict__ bias3,
                                float* __restrict__ basef) {
    int d = blockIdx.x * blockDim.x + threadIdx.x;
    if (d < DV)
        basef[d] = ((float)colsum[d] + bias3[d] > 1.0f) ? 1.0f : 0.0f;
}

// ---------------------------------------------------------------------------
// Compact x row -> list of active d indices (order-independent).
// ---------------------------------------------------------------------------
__global__ __launch_bounds__(256) void compact_x_kernel(
    const float* __restrict__ x, uint16_t* __restrict__ xidx,
    int* __restrict__ xcnt) {
    const int b = blockIdx.x;
    const int t = threadIdx.x;
    __shared__ int cnt;
    if (t == 0) cnt = 0;
    __syncthreads();
    const float4* row = (const float4*)(x + (size_t)b * DV);
    uint16_t* dst = xidx + (size_t)b * DV;
#pragma unroll
    for (int q = 0; q < DV / 4 / 256; q++) {
        int i4 = t + q * 256;
        float4 v = row[i4];
        if (v.x > 0.5f) dst[atomicAdd(&cnt, 1)] = (uint16_t)(i4 * 4);
        if (v.y > 0.5f) dst[atomicAdd(&cnt, 1)] = (uint16_t)(i4 * 4 + 1);
        if (v.z > 0.5f) dst[atomicAdd(&cnt, 1)] = (uint16_t)(i4 * 4 + 2);
        if (v.w > 0.5f) dst[atomicAdd(&cnt, 1)] = (uint16_t)(i4 * 4 + 3);
    }
    __syncthreads();
    if (t == 0) xcnt[b] = cnt;
}

// ---------------------------------------------------------------------------
// Sparse GEMM1 via 3-level saturating bit-counters WITH EARLY EXIT.
// One CTA (128 threads) per batch row; thread t owns h-word t.
// For each active d: bits = wT[d][t]; s3|=s2&bits; s2|=s1&bits; s1|=bits.
// Once ALL counters in the CTA are saturated (s1&s2&s3 == ~0 for every
// thread), no further d can change any state -> break.  Exact for any input
// (the exit fires only when the state is provably fixed).
// ---------------------------------------------------------------------------
__global__ __launch_bounds__(128) void sparse_gemm1_kernel(
    const uint16_t* __restrict__ xidx, const int* __restrict__ xcnt,
    const uint32_t* __restrict__ wT, const float* __restrict__ bias0,
    float* __restrict__ Zf, uint32_t* __restrict__ zmask) {
    const int b = blockIdx.x;
    const int t = threadIdx.x;  // 0..127
    __shared__ uint16_t sidx[128];

    const int n = xcnt[b];
    const uint16_t* idx = xidx + (size_t)b * DV;
    uint32_t s1 = 0, s2 = 0, s3 = 0;

    for (int base = 0; base < n; base += 128) {
        const int m = min(128, n - base);
        __syncthreads();
        if (t < m) sidx[t] = idx[base + t];
        __syncthreads();
        int j = 0;
        for (; j + 8 <= m; j += 8) {
            uint32_t w0 = wT[(size_t)sidx[j + 0] * HW + t];
            uint32_t w1 = wT[(size_t)sidx[j + 1] * HW + t];
            uint32_t w2 = wT[(size_t)sidx[j + 2] * HW + t];
            uint32_t w3 = wT[(size_t)sidx[j + 3] * HW + t];
            uint32_t w4 = wT[(size_t)sidx[j + 4] * HW + t];
            uint32_t w5 = wT[(size_t)sidx[j + 5] * HW + t];
            uint32_t w6 = wT[(size_t)sidx[j + 6] * HW + t];
            uint32_t w7 = wT[(size_t)sidx[j + 7] * HW + t];
            s3 |= s2 & w0; s2 |= s1 & w0; s1 |= w0;
            s3 |= s2 & w1; s2 |= s1 & w1; s1 |= w1;
            s3 |= s2 & w2; s2 |= s1 & w2; s1 |= w2;
            s3 |= s2 & w3; s2 |= s1 & w3; s1 |= w3;
            s3 |= s2 & w4; s2 |= s1 & w4; s1 |= w4;
            s3 |= s2 & w5; s2 |= s1 & w5; s1 |= w5;
            s3 |= s2 & w6; s2 |= s1 & w6; s1 |= w6;
            s3 |= s2 & w7; s2 |= s1 & w7; s1 |= w7;
        }
        for (; j < m; j++) {
            uint32_t wv = wT[(size_t)sidx[j] * HW + t];
            s3 |= s2 & wv; s2 |= s1 & wv; s1 |= wv;
        }
        // Early exit: all 4096 counters saturated -> state frozen forever.
        if (__syncthreads_and((s1 & s2 & s3) == 0xFFFFFFFFu)) break;
    }

    // epilogue: z floats + zmask word (full overwrite -> no memset needed)
    const float* bs = bias0 + t * 32;
    float* dst = Zf + (size_t)b * HV + t * 32;
    uint32_t zm = 0;
#pragma unroll
    for (int q = 0; q < 8; q++) {
        float4 v;
        float* vp = (float*)&v;
#pragma unroll
        for (int c = 0; c < 4; c++) {
            const int bit = q * 4 + c;
            int sat = ((s1 >> bit) & 1) + ((s2 >> bit) & 1) + ((s3 >> bit) & 1);
            float z = ((float)sat + bs[bit] > 1.0f) ? 1.0f : 0.0f;
            vp[c] = z;
            if (z == 0.0f) zm |= 1u << bit;
        }
        *(float4*)(dst + q * 4) = v;
    }
    zmask[(size_t)b * HW + t] = zm;
}

// ---------------------------------------------------------------------------
// Output writer: out[b][d] = (colsum[d] - sum_{h in zeros_b} wb[h][d]
//                             + bias3[d] > 1)
// Clean rows (no zeros; overwhelmingly common) copy the precomputed base row.
// ---------------------------------------------------------------------------
__global__ __launch_bounds__(256) void recon_write_kernel(
    const uint32_t* __restrict__ zmask, const int* __restrict__ colsum,
    const float* __restrict__ basef, const float* __restrict__ bias3,
    const uint32_t* __restrict__ wb, float* __restrict__ out) {
    const int b = blockIdx.x;
    const int t = threadIdx.x;
    __shared__ uint32_t mrow[HW];
    __shared__ int any;
    if (t == 0) any = 0;
    __syncthreads();
    if (t < HW) {
        uint32_t m = zmask[(size_t)b * HW + t];
        mrow[t] = m;
        if (m) atomicOr(&any, 1);
    }
    __syncthreads();

    float* dst = out + (size_t)b * DV;
    if (!any) {
        for (int d4 = t; d4 < DV / 4; d4 += 256)
            ((float4*)dst)[d4] = ((const float4*)basef)[d4];
        return;
    }
    // slow path: exact integer correction using bit-packed wb rows.
    int cnt[DV / 256];
#pragma unroll
    for (int i = 0; i < DV / 256; i++) cnt[i] = colsum[t + i * 256];
    for (int wq = 0; wq < HW; wq++) {
        uint32_t m = mrow[wq];
        while (m) {
            int bit = __ffs(m) - 1;
            m &= m - 1;
            const uint32_t* wrow = wb + (size_t)(wq * 32 + bit) * DW;
#pragma unroll
            for (int i = 0; i < DV / 256; i++) {
                int d = t + i * 256;
                cnt[i] -= (wrow[d >> 5] >> (d & 31)) & 1;
            }
        }
    }
#pragma unroll
    for (int i = 0; i < DV / 256; i++) {
        int d = t + i * 256;
        dst[d] = ((float)cnt[i] + bias3[d] > 1.0f) ? 1.0f : 0.0f;
    }
}

// ---------------------------------------------------------------------------
// Classifier: class[b][l] = rowsum[l] - sum_{h in zeros_b} clf[l][h]
// (double accumulation, deterministic scan order).
// ---------------------------------------------------------------------------
__global__ __launch_bounds__(128) void clf_write_kernel(
    const uint32_t* __restrict__ zmask, const double* __restrict__ rowsum,
    const float* __restrict__ clf, float* __restrict__ out) {
    const int b = blockIdx.x;
    const int l = threadIdx.x;  // 0..127
    __shared__ uint32_t mrow[HW];
    mrow[l] = zmask[(size_t)b * HW + l];
    __syncthreads();

    double corr = 0.0;
    for (int wq = 0; wq < HW; wq++) {
        uint32_t m = mrow[wq];
        while (m) {
            int bit = __ffs(m) - 1;
            m &= m - 1;
            corr += (double)clf[(size_t)l * HV + wq * 32 + bit];
        }
    }
    out[(size_t)b * LV + l] = (float)(rowsum[l] - corr);
}

// ---------------------------------------------------------------------------
// Launch.  Output layout: [output (B*D) | classification (B*L) | z (B*H)].
// ---------------------------------------------------------------------------
extern "C" void kernel_launch(void* const* d_in, const int* in_sizes, int n_in,
                              void* d_out, int out_size) {
    const float* x     = (const float*)d_in[0];
    const float* w     = (const float*)d_in[1];
    const float* bias0 = (const float*)d_in[2];
    const float* bias3 = (const float*)d_in[3];
    const float* clf   = (const float*)d_in[4];

    float* out        = (float*)d_out;
    float* out_output = out;
    float* out_class  = out + (size_t)BV * DV;
    float* out_z      = out + (size_t)BV * DV + (size_t)BV * LV;

    uint32_t *wT, *wb, *zmask;
    uint16_t* xidx;
    int *xcnt, *colsum;
    double* rowsum;
    float* basef;
    cudaGetSymbolAddress((void**)&wT, g_wT_bits);
    cudaGetSymbolAddress((void**)&wb, g_w_bits);
    cudaGetSymbolAddress((void**)&xidx, g_xidx);
    cudaGetSymbolAddress((void**)&xcnt, g_xcnt);
    cudaGetSymbolAddress((void**)&colsum, g_colsum);
    cudaGetSymbolAddress((void**)&zmask, g_zmask);
    cudaGetSymbolAddress((void**)&rowsum, g_rowsum);
    cudaGetSymbolAddress((void**)&basef, g_basef);

    // 0) zero the one accumulator that needs it
    cudaMemsetAsync(colsum, 0, DV * sizeof(int));

    // 1) pack weights (both layouts) + colsum; clf row sums; x compaction
    pack_w_kernel<<<dim3(DV / 256, HV / 32), 256>>>(w, wT, wb, colsum);
    clf_rowsum_kernel<<<LV, 256>>>(clf, rowsum);
    compact_x_kernel<<<BV, 256>>>(x, xidx, xcnt);
    base_row_kernel<<<DV / 256, 256>>>(colsum, bias3, basef);

    // 2) sparse GEMM1: z + zmask via saturating bit-counters + early exit
    sparse_gemm1_kernel<<<BV, 128>>>(xidx, xcnt, wT, bias0, out_z, zmask);

    // 3) output = (colsum - corrections + bias3 > 1)   [exact, integer]
    recon_write_kernel<<<BV, 256>>>(zmask, colsum, basef, bias3, wb, out_output);

    // 4) classification = rowsum - corrections          [double, deterministic]
    clf_write_kernel<<<BV, 128>>>(zmask, rowsum, clf, out_class);
}

// round 15
// speedup vs baseline: 8.4663x; 1.0968x over previous
#include <cuda_runtime.h>
#include <cstdint>

// Problem constants (DiffnapsNet_42030549959310)
#define BV 4096   // batch
#define DV 8192   // data dim
#define HV 4096   // hidden
#define LV 128    // labels

#define HW (HV / 32)      // 128  : wT words per d / zmask words per row
#define DW (DV / 32)      // 256  : w_bits words per h-row

// ---------------------------------------------------------------------------
// Scratch (device globals; no allocation allowed)
// ---------------------------------------------------------------------------
__device__ __align__(16) uint32_t g_wT_bits[(size_t)DV * HW];  // [D][H/32] bits
__device__ __align__(16) uint32_t g_w_bits[(size_t)HV * DW];   // [H][D/32] bits
__device__ __align__(16) uint16_t g_xidx[(size_t)BV * DV];     // active-d lists
__device__ __align__(16) int      g_xcnt[BV];
__device__ __align__(16) int      g_colsum[DV];                // sum_h wb[h][d]
__device__ __align__(16) double   g_rowsum[LV];                // sum_h clf[l][h]

// ---------------------------------------------------------------------------
// Fused prep kernel (block-specialized):
//   blocks [0, BV)            : compact x row b -> xidx/xcnt
//   blocks [BV, BV+4096)      : pack enc_weight bits (both layouts) + colsum
//   blocks [BV+4096, +LV)     : clf row sums (double, fixed-order reduction)
// All three roles stream independent data concurrently.
// ---------------------------------------------------------------------------
__global__ __launch_bounds__(256) void prep_kernel(
    const float* __restrict__ x, const float* __restrict__ w,
    const float* __restrict__ clf,
    uint16_t* __restrict__ xidx, int* __restrict__ xcnt,
    uint32_t* __restrict__ wT, uint32_t* __restrict__ wb,
    int* __restrict__ colsum, double* __restrict__ rowsum) {
    const int bid = blockIdx.x;
    const int t   = threadIdx.x;
    __shared__ int cnt;
    __shared__ double sm[256];

    if (bid < BV) {
        // ---- compact x row ----
        const int b = bid;
        if (t == 0) cnt = 0;
        __syncthreads();
        const float4* row = (const float4*)(x + (size_t)b * DV);
        uint16_t* dst = xidx + (size_t)b * DV;
#pragma unroll
        for (int q = 0; q < DV / 4 / 256; q++) {
            int i4 = t + q * 256;
            float4 v = row[i4];
            if (v.x > 0.5f) dst[atomicAdd(&cnt, 1)] = (uint16_t)(i4 * 4);
            if (v.y > 0.5f) dst[atomicAdd(&cnt, 1)] = (uint16_t)(i4 * 4 + 1);
            if (v.z > 0.5f) dst[atomicAdd(&cnt, 1)] = (uint16_t)(i4 * 4 + 2);
            if (v.w > 0.5f) dst[atomicAdd(&cnt, 1)] = (uint16_t)(i4 * 4 + 3);
        }
        __syncthreads();
        if (t == 0) xcnt[b] = cnt;
    } else if (bid < BV + 4096) {
        // ---- pack enc_weight ----
        const int e    = bid - BV;
        const int d    = (e & 31) * 256 + t;  // 0..DV-1
        const int hy   = e >> 5;              // 0..127
        const int lane = t & 31;
        const float* col = w + (size_t)hy * 32 * DV + d;
        uint32_t v = 0, mymask = 0;
#pragma unroll
        for (int i = 0; i < 32; i++) {
            bool b8 = col[(size_t)i * DV] > 0.5f;
            if (b8) v |= 1u << i;
            uint32_t m = __ballot_sync(0xffffffffu, b8);
            if (lane == i) mymask = m;
        }
        wT[(size_t)d * HW + hy] = v;
        wb[(size_t)(hy * 32 + lane) * DW + (d >> 5)] = mymask;
        atomicAdd(&colsum[d], __popc(v));
    } else {
        // ---- clf row sums ----
        const int l = bid - (BV + 4096);
        double p = 0.0;
        for (int k = t; k < HV; k += 256) p += (double)clf[(size_t)l * HV + k];
        sm[t] = p;
        __syncthreads();
        for (int s = 128; s > 0; s >>= 1) {
            if (t < s) sm[t] += sm[t + s];
            __syncthreads();
        }
        if (t == 0) rowsum[l] = sm[0];
    }
}

// ---------------------------------------------------------------------------
// Fused main kernel: one CTA (128 threads) per batch row.
//   Phase 1: z counts via 3-level saturating bit-counters, early exit every
//            32 indices (state frozen once all 4096 counters reach 3).
//   Phase 2: z = ((float)min(cnt,3) + bias0 > 1) -> out_z  (bit-exact).
//   Phase 3: zero list (built by thread 0 in fixed h order -> deterministic).
//   Phase 4: recon out[b][d] = (colsum[d] - corrections + bias3[d] > 1).
//   Phase 5: class[b][l] = rowsum[l] - sum_{h in zeros} clf[l][h]  (double).
// ---------------------------------------------------------------------------
__global__ __launch_bounds__(128) void main_kernel(
    const uint16_t* __restrict__ xidx, const int* __restrict__ xcnt,
    const uint32_t* __restrict__ wT, const uint32_t* __restrict__ wb,
    const int* __restrict__ colsum, const float* __restrict__ bias0,
    const float* __restrict__ bias3, const float* __restrict__ clf,
    const double* __restrict__ rowsum,
    float* __restrict__ out_output, float* __restrict__ out_class,
    float* __restrict__ out_z) {
    const int b = blockIdx.x;
    const int t = threadIdx.x;  // 0..127
    __shared__ uint16_t sidx[32];
    __shared__ uint32_t mrow[HW];
    __shared__ uint16_t zlist[HV];
    __shared__ int nz;

    // ---- Phase 1: saturating counters with fine-grained early exit ----
    const int n = xcnt[b];
    const uint16_t* idx = xidx + (size_t)b * DV;
    uint32_t s1 = 0, s2 = 0, s3 = 0;
    for (int base = 0; base < n; base += 32) {
        const int m = min(32, n - base);
        __syncthreads();
        if (t < m) sidx[t] = idx[base + t];
        __syncthreads();
        int j = 0;
        for (; j + 4 <= m; j += 4) {
            uint32_t w0 = wT[(size_t)sidx[j + 0] * HW + t];
            uint32_t w1 = wT[(size_t)sidx[j + 1] * HW + t];
            uint32_t w2 = wT[(size_t)sidx[j + 2] * HW + t];
            uint32_t w3 = wT[(size_t)sidx[j + 3] * HW + t];
            s3 |= s2 & w0; s2 |= s1 & w0; s1 |= w0;
            s3 |= s2 & w1; s2 |= s1 & w1; s1 |= w1;
            s3 |= s2 & w2; s2 |= s1 & w2; s1 |= w2;
            s3 |= s2 & w3; s2 |= s1 & w3; s1 |= w3;
        }
        for (; j < m; j++) {
            uint32_t wv = wT[(size_t)sidx[j] * HW + t];
            s3 |= s2 & wv; s2 |= s1 & wv; s1 |= wv;
        }
        if (__syncthreads_and((s1 & s2 & s3) == 0xFFFFFFFFu)) break;
    }

    // ---- Phase 2: z epilogue (full overwrite) ----
    const float* bs = bias0 + t * 32;
    float* zdst = out_z + (size_t)b * HV + t * 32;
    uint32_t zm = 0;
#pragma unroll
    for (int q = 0; q < 8; q++) {
        float4 v;
        float* vp = (float*)&v;
#pragma unroll
        for (int c = 0; c < 4; c++) {
            const int bit = q * 4 + c;
            int sat = ((s1 >> bit) & 1) + ((s2 >> bit) & 1) + ((s3 >> bit) & 1);
            float z = ((float)sat + bs[bit] > 1.0f) ? 1.0f : 0.0f;
            vp[c] = z;
            if (z == 0.0f) zm |= 1u << bit;
        }
        *(float4*)(zdst + q * 4) = v;
    }
    mrow[t] = zm;
    if (t == 0) nz = 0;
    __syncthreads();

    // ---- Phase 3: deterministic zero list (thread 0, fixed h order) ----
    if (t == 0) {
        int k = 0;
        for (int wq = 0; wq < HW; wq++) {
            uint32_t m = mrow[wq];
            while (m) {
                int bit = __ffs(m) - 1;
                m &= m - 1;
                zlist[k++] = (uint16_t)(wq * 32 + bit);
            }
        }
        nz = k;
    }
    __syncthreads();
    const int znum = nz;

    // ---- Phase 4: reconstruction output ----
    float* dst = out_output + (size_t)b * DV;
    if (znum == 0) {
#pragma unroll
        for (int i = 0; i < 16; i++) {
            const int d4 = t + i * 128;
            const int d = d4 * 4;
            float4 o;
            o.x = ((float)colsum[d]     + bias3[d]     > 1.0f) ? 1.0f : 0.0f;
            o.y = ((float)colsum[d + 1] + bias3[d + 1] > 1.0f) ? 1.0f : 0.0f;
            o.z = ((float)colsum[d + 2] + bias3[d + 2] > 1.0f) ? 1.0f : 0.0f;
            o.w = ((float)colsum[d + 3] + bias3[d + 3] > 1.0f) ? 1.0f : 0.0f;
            ((float4*)dst)[d4] = o;
        }
    } else {
        for (int i = 0; i < 16; i++) {
            const int d4 = t + i * 128;
            const int d = d4 * 4;
            float4 o;
            float* op = (float*)&o;
#pragma unroll
            for (int c = 0; c < 4; c++) {
                const int dd = d + c;
                int cnt = colsum[dd];
                for (int k = 0; k < znum; k++) {
                    const int h = zlist[k];
                    cnt -= (wb[(size_t)h * DW + (dd >> 5)] >> (dd & 31)) & 1;
                }
                op[c] = ((float)cnt + bias3[dd] > 1.0f) ? 1.0f : 0.0f;
            }
            ((float4*)dst)[d4] = o;
        }
    }

    // ---- Phase 5: classifier (deterministic double accumulation) ----
    double corr = 0.0;
    for (int k = 0; k < znum; k++)
        corr += (double)clf[(size_t)t * HV + zlist[k]];
    out_class[(size_t)b * LV + t] = (float)(rowsum[t] - corr);
}

// ---------------------------------------------------------------------------
// Launch.  Output layout: [output (B*D) | classification (B*L) | z (B*H)].
// ---------------------------------------------------------------------------
extern "C" void kernel_launch(void* const* d_in, const int* in_sizes, int n_in,
                              void* d_out, int out_size) {
    const float* x     = (const float*)d_in[0];
    const float* w     = (const float*)d_in[1];
    const float* bias0 = (const float*)d_in[2];
    const float* bias3 = (const float*)d_in[3];
    const float* clf   = (const float*)d_in[4];

    float* out        = (float*)d_out;
    float* out_output = out;
    float* out_class  = out + (size_t)BV * DV;
    float* out_z      = out + (size_t)BV * DV + (size_t)BV * LV;

    uint32_t *wT, *wb;
    uint16_t* xidx;
    int *xcnt, *colsum;
    double* rowsum;
    cudaGetSymbolAddress((void**)&wT, g_wT_bits);
    cudaGetSymbolAddress((void**)&wb, g_w_bits);
    cudaGetSymbolAddress((void**)&xidx, g_xidx);
    cudaGetSymbolAddress((void**)&xcnt, g_xcnt);
    cudaGetSymbolAddress((void**)&colsum, g_colsum);
    cudaGetSymbolAddress((void**)&rowsum, g_rowsum);

    // 0) zero the one accumulator that needs it
    cudaMemsetAsync(colsum, 0, DV * sizeof(int));

    // 1) fused prep: compact x  |  pack w (both layouts) + colsum  |  clf sums
    prep_kernel<<<BV + 4096 + LV, 256>>>(x, w, clf, xidx, xcnt, wT, wb,
                                         colsum, rowsum);

    // 2) fused main: z + zmask -> recon output + classification, per row
    main_kernel<<<BV, 128>>>(xidx, xcnt, wT, wb, colsum, bias0, bias3, clf,
                             rowsum, out_output, out_class, out_z);
}

// round 16
// speedup vs baseline: 12.4725x; 1.4732x over previous
#include <cuda_runtime.h>
#include <cstdint>

// Problem constants (DiffnapsNet_42030549959310)
#define BV 4096   // batch
#define DV 8192   // data dim
#define HV 4096   // hidden
#define LV 128    // labels

#define HW (HV / 32)      // 128  : wT words per d / zmask words per row
#define DW (DV / 32)      // 256  : w_bits words per h-row

// ---------------------------------------------------------------------------
// Scratch (device globals; no allocation allowed)
// ---------------------------------------------------------------------------
__device__ __align__(16) uint32_t g_wT_bits[(size_t)DV * HW];  // [D][H/32] bits
__device__ __align__(16) uint32_t g_w_bits[(size_t)HV * DW];   // [H][D/32] bits
__device__ __align__(16) uint16_t g_xidx[(size_t)BV * DV];     // active-d lists
__device__ __align__(16) int      g_xcnt[BV];
__device__ __align__(16) int      g_colsum[DV];                // sum_h wb[h][d]
__device__ __align__(16) double   g_rowsum[LV];                // sum_h clf[l][h]
__device__ __align__(16) float    g_basef[DV];                 // thresholded base row

// ---------------------------------------------------------------------------
// Fused prep kernel (block-specialized):
//   blocks [0, BV)            : compact x row b -> xidx/xcnt
//   blocks [BV, BV+4096)      : pack enc_weight bits (both layouts) + colsum
//   blocks [BV+4096, +LV)     : clf row sums (double, fixed-order reduction)
// ---------------------------------------------------------------------------
__global__ __launch_bounds__(256) void prep_kernel(
    const float* __restrict__ x, const float* __restrict__ w,
    const float* __restrict__ clf,
    uint16_t* __restrict__ xidx, int* __restrict__ xcnt,
    uint32_t* __restrict__ wT, uint32_t* __restrict__ wb,
    int* __restrict__ colsum, double* __restrict__ rowsum) {
    const int bid = blockIdx.x;
    const int t   = threadIdx.x;
    __shared__ int cnt;
    __shared__ double sm[256];

    if (bid < BV) {
        // ---- compact x row ----
        const int b = bid;
        if (t == 0) cnt = 0;
        __syncthreads();
        const float4* row = (const float4*)(x + (size_t)b * DV);
        uint16_t* dst = xidx + (size_t)b * DV;
#pragma unroll
        for (int q = 0; q < DV / 4 / 256; q++) {
            int i4 = t + q * 256;
            float4 v = row[i4];
            if (v.x > 0.5f) dst[atomicAdd(&cnt, 1)] = (uint16_t)(i4 * 4);
            if (v.y > 0.5f) dst[atomicAdd(&cnt, 1)] = (uint16_t)(i4 * 4 + 1);
            if (v.z > 0.5f) dst[atomicAdd(&cnt, 1)] = (uint16_t)(i4 * 4 + 2);
            if (v.w > 0.5f) dst[atomicAdd(&cnt, 1)] = (uint16_t)(i4 * 4 + 3);
        }
        __syncthreads();
        if (t == 0) xcnt[b] = cnt;
    } else if (bid < BV + 4096) {
        // ---- pack enc_weight ----
        const int e    = bid - BV;
        const int d    = (e & 31) * 256 + t;  // 0..DV-1
        const int hy   = e >> 5;              // 0..127
        const int lane = t & 31;
        const float* col = w + (size_t)hy * 32 * DV + d;
        uint32_t v = 0, mymask = 0;
#pragma unroll
        for (int i = 0; i < 32; i++) {
            bool b8 = col[(size_t)i * DV] > 0.5f;
            if (b8) v |= 1u << i;
            uint32_t m = __ballot_sync(0xffffffffu, b8);
            if (lane == i) mymask = m;
        }
        wT[(size_t)d * HW + hy] = v;
        wb[(size_t)(hy * 32 + lane) * DW + (d >> 5)] = mymask;
        atomicAdd(&colsum[d], __popc(v));
    } else {
        // ---- clf row sums ----
        const int l = bid - (BV + 4096);
        double p = 0.0;
        for (int k = t; k < HV; k += 256) p += (double)clf[(size_t)l * HV + k];
        sm[t] = p;
        __syncthreads();
        for (int s = 128; s > 0; s >>= 1) {
            if (t < s) sm[t] += sm[t + s];
            __syncthreads();
        }
        if (t == 0) rowsum[l] = sm[0];
    }
}

// Thresholded base reconstruction row: basef[d] = (colsum[d]+bias3[d] > 1).
__global__ void base_row_kernel(const int* __restrict__ colsum,
                                const float* __restrict__ bias3,
                                float* __restrict__ basef) {
    int d = blockIdx.x * blockDim.x + threadIdx.x;
    if (d < DV)
        basef[d] = ((float)colsum[d] + bias3[d] > 1.0f) ? 1.0f : 0.0f;
}

// ---------------------------------------------------------------------------
// Fused main kernel: one CTA (128 threads) per batch row.
//   Phase 1: z counts via 3-level saturating bit-counters, early exit every
//            32 indices (state frozen once all 4096 counters reach 3).
//   Phase 2: z = ((float)min(cnt,3) + bias0 > 1) -> out_z  (bit-exact).
//   Phase 3: zero list (thread 0, fixed h order -> deterministic).
//   Phase 4: recon; znum==0 rows copy basef (vector L1 ops), else exact
//            integer correction with one wb word per 4 outputs.
//   Phase 5: class[b][l] = rowsum[l] - sum_{h in zeros} clf[l][h]  (double).
// ---------------------------------------------------------------------------
__global__ __launch_bounds__(128) void main_kernel(
    const uint16_t* __restrict__ xidx, const int* __restrict__ xcnt,
    const uint32_t* __restrict__ wT, const uint32_t* __restrict__ wb,
    const int* __restrict__ colsum, const float* __restrict__ bias0,
    const float* __restrict__ bias3, const float* __restrict__ clf,
    const double* __restrict__ rowsum, const float* __restrict__ basef,
    float* __restrict__ out_output, float* __restrict__ out_class,
    float* __restrict__ out_z) {
    const int b = blockIdx.x;
    const int t = threadIdx.x;  // 0..127
    __shared__ uint16_t sidx[32];
    __shared__ uint32_t mrow[HW];
    __shared__ uint16_t zlist[HV];
    __shared__ int nz;

    // ---- Phase 1: saturating counters with fine-grained early exit ----
    const int n = xcnt[b];
    const uint16_t* idx = xidx + (size_t)b * DV;
    uint32_t s1 = 0, s2 = 0, s3 = 0;
    for (int base = 0; base < n; base += 32) {
        const int m = min(32, n - base);
        __syncthreads();
        if (t < m) sidx[t] = idx[base + t];
        __syncthreads();
        int j = 0;
        for (; j + 4 <= m; j += 4) {
            uint32_t w0 = wT[(size_t)sidx[j + 0] * HW + t];
            uint32_t w1 = wT[(size_t)sidx[j + 1] * HW + t];
            uint32_t w2 = wT[(size_t)sidx[j + 2] * HW + t];
            uint32_t w3 = wT[(size_t)sidx[j + 3] * HW + t];
            s3 |= s2 & w0; s2 |= s1 & w0; s1 |= w0;
            s3 |= s2 & w1; s2 |= s1 & w1; s1 |= w1;
            s3 |= s2 & w2; s2 |= s1 & w2; s1 |= w2;
            s3 |= s2 & w3; s2 |= s1 & w3; s1 |= w3;
        }
        for (; j < m; j++) {
            uint32_t wv = wT[(size_t)sidx[j] * HW + t];
            s3 |= s2 & wv; s2 |= s1 & wv; s1 |= wv;
        }
        if (__syncthreads_and((s1 & s2 & s3) == 0xFFFFFFFFu)) break;
    }

    // ---- Phase 2: z epilogue (vectorized bias loads, full overwrite) ----
    const float4* bs4 = (const float4*)(bias0 + t * 32);
    float* zdst = out_z + (size_t)b * HV + t * 32;
    uint32_t zm = 0;
#pragma unroll
    for (int q = 0; q < 8; q++) {
        float4 bsv = bs4[q];
        const float* bp = (const float*)&bsv;
        float4 v;
        float* vp = (float*)&v;
#pragma unroll
        for (int c = 0; c < 4; c++) {
            const int bit = q * 4 + c;
            int sat = ((s1 >> bit) & 1) + ((s2 >> bit) & 1) + ((s3 >> bit) & 1);
            float z = ((float)sat + bp[c] > 1.0f) ? 1.0f : 0.0f;
            vp[c] = z;
            if (z == 0.0f) zm |= 1u << bit;
        }
        *(float4*)(zdst + q * 4) = v;
    }
    mrow[t] = zm;
    if (t == 0) nz = 0;
    __syncthreads();

    // ---- Phase 3: deterministic zero list (thread 0, fixed h order) ----
    if (t == 0) {
        int k = 0;
        for (int wq = 0; wq < HW; wq++) {
            uint32_t m = mrow[wq];
            while (m) {
                int bit = __ffs(m) - 1;
                m &= m - 1;
                zlist[k++] = (uint16_t)(wq * 32 + bit);
            }
        }
        nz = k;
    }
    __syncthreads();
    const int znum = nz;

    // ---- Phase 4: reconstruction output ----
    float4* dst4 = (float4*)(out_output + (size_t)b * DV);
    if (znum == 0) {
        const float4* bf4 = (const float4*)basef;
#pragma unroll
        for (int i = 0; i < 16; i++) {
            const int d4 = t + i * 128;
            dst4[d4] = bf4[d4];
        }
    } else {
        const int4* cs4 = (const int4*)colsum;
        const float4* b34 = (const float4*)bias3;
        for (int i = 0; i < 16; i++) {
            const int d4 = t + i * 128;
            const int d = d4 * 4;
            int4 cs = cs4[d4];
            float4 b3 = b34[d4];
            int c0 = cs.x, c1 = cs.y, c2 = cs.z, c3 = cs.w;
            const int wq = d >> 5;       // same 32-bit word for all 4 outputs
            const int sh = d & 31;       // aligned: sh in {0,4,...,28}
            for (int k = 0; k < znum; k++) {
                const uint32_t wv = wb[(size_t)zlist[k] * DW + wq] >> sh;
                c0 -= wv & 1;
                c1 -= (wv >> 1) & 1;
                c2 -= (wv >> 2) & 1;
                c3 -= (wv >> 3) & 1;
            }
            float4 o;
            o.x = ((float)c0 + b3.x > 1.0f) ? 1.0f : 0.0f;
            o.y = ((float)c1 + b3.y > 1.0f) ? 1.0f : 0.0f;
            o.z = ((float)c2 + b3.z > 1.0f) ? 1.0f : 0.0f;
            o.w = ((float)c3 + b3.w > 1.0f) ? 1.0f : 0.0f;
            dst4[d4] = o;
        }
    }

    // ---- Phase 5: classifier (deterministic double accumulation) ----
    double corr = 0.0;
    for (int k = 0; k < znum; k++)
        corr += (double)clf[(size_t)t * HV + zlist[k]];
    out_class[(size_t)b * LV + t] = (float)(rowsum[t] - corr);
}

// ---------------------------------------------------------------------------
// Launch.  Output layout: [output (B*D) | classification (B*L) | z (B*H)].
// ---------------------------------------------------------------------------
extern "C" void kernel_launch(void* const* d_in, const int* in_sizes, int n_in,
                              void* d_out, int out_size) {
    const float* x     = (const float*)d_in[0];
    const float* w     = (const float*)d_in[1];
    const float* bias0 = (const float*)d_in[2];
    const float* bias3 = (const float*)d_in[3];
    const float* clf   = (const float*)d_in[4];

    float* out        = (float*)d_out;
    float* out_output = out;
    float* out_class  = out + (size_t)BV * DV;
    float* out_z      = out + (size_t)BV * DV + (size_t)BV * LV;

    uint32_t *wT, *wb;
    uint16_t* xidx;
    int *xcnt, *colsum;
    double* rowsum;
    float* basef;
    cudaGetSymbolAddress((void**)&wT, g_wT_bits);
    cudaGetSymbolAddress((void**)&wb, g_w_bits);
    cudaGetSymbolAddress((void**)&xidx, g_xidx);
    cudaGetSymbolAddress((void**)&xcnt, g_xcnt);
    cudaGetSymbolAddress((void**)&colsum, g_colsum);
    cudaGetSymbolAddress((void**)&rowsum, g_rowsum);
    cudaGetSymbolAddress((void**)&basef, g_basef);

    // 0) zero the one accumulator that needs it
    cudaMemsetAsync(colsum, 0, DV * sizeof(int));

    // 1) fused prep: compact x  |  pack w (both layouts) + colsum  |  clf sums
    prep_kernel<<<BV + 4096 + LV, 256>>>(x, w, clf, xidx, xcnt, wT, wb,
                                         colsum, rowsum);

    // 1b) thresholded base reconstruction row
    base_row_kernel<<<DV / 256, 256>>>(colsum, bias3, basef);

    // 2) fused main: z -> recon output + classification, per row
    main_kernel<<<BV, 128>>>(xidx, xcnt, wT, wb, colsum, bias0, bias3, clf,
                             rowsum, basef, out_output, out_class, out_z);
}

// round 17
// speedup vs baseline: 14.3991x; 1.1545x over previous
#include <cuda_runtime.h>
#include <cstdint>

// Problem constants (DiffnapsNet_42030549959310)
#define BV 4096   // batch
#define DV 8192   // data dim
#define HV 4096   // hidden
#define LV 128    // labels

#define HW (HV / 32)      // 128 : wT words per d / zmask words per row

// ---------------------------------------------------------------------------
// Scratch (device globals; no allocation allowed)
// ---------------------------------------------------------------------------
__device__ __align__(16) uint32_t g_wT_bits[(size_t)DV * HW];  // [D][H/32] bits
__device__ __align__(16) int      g_colsum[DV];                // sum_h wb[h][d]
__device__ __align__(16) double   g_rowsum[LV];                // sum_h clf[l][h]
__device__ __align__(16) float    g_basef[DV];                 // thresholded base row

// ---------------------------------------------------------------------------
// Fused prep kernel (block-specialized):
//   blocks [0, 4096)      : pack enc_weight bits -> wT + colsum
//   blocks [4096, +LV)    : clf row sums (double, fixed-order reduction)
// ---------------------------------------------------------------------------
__global__ __launch_bounds__(256) void prep_kernel(
    const float* __restrict__ w, const float* __restrict__ clf,
    uint32_t* __restrict__ wT, int* __restrict__ colsum,
    double* __restrict__ rowsum) {
    const int bid = blockIdx.x;
    const int t   = threadIdx.x;

    if (bid < 4096) {
        // ---- pack enc_weight: column d, h-group hy*32..+31 ----
        const int d  = (bid & 31) * 256 + t;  // 0..DV-1
        const int hy = bid >> 5;              // 0..127
        const float* col = w + (size_t)hy * 32 * DV + d;
        uint32_t v = 0;
#pragma unroll
        for (int i = 0; i < 32; i++)
            if (col[(size_t)i * DV] > 0.5f) v |= 1u << i;
        wT[(size_t)d * HW + hy] = v;
        atomicAdd(&colsum[d], __popc(v));
    } else {
        // ---- clf row sums ----
        __shared__ double sm[256];
        const int l = bid - 4096;
        double p = 0.0;
        for (int k = t; k < HV; k += 256) p += (double)clf[(size_t)l * HV + k];
        sm[t] = p;
        __syncthreads();
        for (int s = 128; s > 0; s >>= 1) {
            if (t < s) sm[t] += sm[t + s];
            __syncthreads();
        }
        if (t == 0) rowsum[l] = sm[0];
    }
}

// Thresholded base reconstruction row: basef[d] = (colsum[d]+bias3[d] > 1).
__global__ void base_row_kernel(const int* __restrict__ colsum,
                                const float* __restrict__ bias3,
                                float* __restrict__ basef) {
    int d = blockIdx.x * blockDim.x + threadIdx.x;
    if (d < DV)
        basef[d] = ((float)colsum[d] + bias3[d] > 1.0f) ? 1.0f : 0.0f;
}

// ---------------------------------------------------------------------------
// Fused main kernel: one CTA (128 threads) per batch row.
//   Phase 1: on-the-fly sparse scan of x (512-element chunks, warp-ballot
//            compaction) feeding 3-level saturating bit-counters with early
//            exit (state frozen once all 4096 counters reach 3).  Typical
//            rows touch only the first chunk (~2 KB of x instead of 32 KB).
//            Counter state = f(count) only -> compaction order irrelevant.
//   Phase 2: z = ((float)min(cnt,3) + bias0 > 1) -> out_z  (bit-exact).
//   Phase 3: zero list (thread 0, fixed h order -> deterministic).
//   Phase 4: recon; znum==0 rows copy basef, else exact integer correction
//            gathering bits from wT.
//   Phase 5: class[b][l] = rowsum[l] - sum_{h in zeros} clf[l][h]  (double).
// ---------------------------------------------------------------------------
__global__ __launch_bounds__(128) void main_kernel(
    const float* __restrict__ x, const uint32_t* __restrict__ wT,
    const int* __restrict__ colsum, const float* __restrict__ bias0,
    const float* __restrict__ bias3, const float* __restrict__ clf,
    const double* __restrict__ rowsum, const float* __restrict__ basef,
    float* __restrict__ out_output, float* __restrict__ out_class,
    float* __restrict__ out_z) {
    const int b = blockIdx.x;
    const int t = threadIdx.x;  // 0..127
    const int lane = t & 31;
    const uint32_t ltmask = (1u << lane) - 1u;
    __shared__ uint16_t list[512];
    __shared__ int lcnt;
    __shared__ uint32_t mrow[HW];
    __shared__ uint16_t zlist[HV];
    __shared__ int nz;

    // ---- Phase 1: chunked sparse scan + saturating counters ----
    const float4* xr = (const float4*)(x + (size_t)b * DV);
    uint32_t s1 = 0, s2 = 0, s3 = 0;
    for (int ch = 0; ch < DV / 512; ch++) {
        if (t == 0) lcnt = 0;
        __syncthreads();
        float4 v = xr[ch * 128 + t];
        const int d0 = (ch * 128 + t) * 4;
        // warp-aggregated compaction, one component at a time
        float comp[4] = {v.x, v.y, v.z, v.w};
#pragma unroll
        for (int c = 0; c < 4; c++) {
            bool p = comp[c] > 0.5f;
            uint32_t mk = __ballot_sync(0xffffffffu, p);
            int base;
            if (lane == 0) base = atomicAdd(&lcnt, __popc(mk));
            base = __shfl_sync(0xffffffffu, base, 0);
            if (p) list[base + __popc(mk & ltmask)] = (uint16_t)(d0 + c);
        }
        __syncthreads();
        const int m = lcnt;
        int j = 0;
        for (; j + 4 <= m; j += 4) {
            uint32_t w0 = wT[(size_t)list[j + 0] * HW + t];
            uint32_t w1 = wT[(size_t)list[j + 1] * HW + t];
            uint32_t w2 = wT[(size_t)list[j + 2] * HW + t];
            uint32_t w3 = wT[(size_t)list[j + 3] * HW + t];
            s3 |= s2 & w0; s2 |= s1 & w0; s1 |= w0;
            s3 |= s2 & w1; s2 |= s1 & w1; s1 |= w1;
            s3 |= s2 & w2; s2 |= s1 & w2; s1 |= w2;
            s3 |= s2 & w3; s2 |= s1 & w3; s1 |= w3;
        }
        for (; j < m; j++) {
            uint32_t wv = wT[(size_t)list[j] * HW + t];
            s3 |= s2 & wv; s2 |= s1 & wv; s1 |= wv;
        }
        if (__syncthreads_and((s1 & s2 & s3) == 0xFFFFFFFFu)) break;
    }

    // ---- Phase 2: z epilogue (vectorized bias loads, full overwrite) ----
    const float4* bs4 = (const float4*)(bias0 + t * 32);
    float* zdst = out_z + (size_t)b * HV + t * 32;
    uint32_t zm = 0;
#pragma unroll
    for (int q = 0; q < 8; q++) {
        float4 bsv = bs4[q];
        const float* bp = (const float*)&bsv;
        float4 v;
        float* vp = (float*)&v;
#pragma unroll
        for (int c = 0; c < 4; c++) {
            const int bit = q * 4 + c;
            int sat = ((s1 >> bit) & 1) + ((s2 >> bit) & 1) + ((s3 >> bit) & 1);
            float z = ((float)sat + bp[c] > 1.0f) ? 1.0f : 0.0f;
            vp[c] = z;
            if (z == 0.0f) zm |= 1u << bit;
        }
        *(float4*)(zdst + q * 4) = v;
    }
    mrow[t] = zm;
    if (t == 0) nz = 0;
    __syncthreads();

    // ---- Phase 3: deterministic zero list (thread 0, fixed h order) ----
    if (t == 0) {
        int k = 0;
        for (int wq = 0; wq < HW; wq++) {
            uint32_t m = mrow[wq];
            while (m) {
                int bit = __ffs(m) - 1;
                m &= m - 1;
                zlist[k++] = (uint16_t)(wq * 32 + bit);
            }
        }
        nz = k;
    }
    __syncthreads();
    const int znum = nz;

    // ---- Phase 4: reconstruction output ----
    float4* dst4 = (float4*)(out_output + (size_t)b * DV);
    if (znum == 0) {
        const float4* bf4 = (const float4*)basef;
#pragma unroll
        for (int i = 0; i < 16; i++) {
            const int d4 = t + i * 128;
            dst4[d4] = bf4[d4];
        }
    } else {
        const int4* cs4 = (const int4*)colsum;
        const float4* b34 = (const float4*)bias3;
        for (int i = 0; i < 16; i++) {
            const int d4 = t + i * 128;
            const int d = d4 * 4;
            int4 cs = cs4[d4];
            float4 b3 = b34[d4];
            int c0 = cs.x, c1 = cs.y, c2 = cs.z, c3 = cs.w;
            for (int k = 0; k < znum; k++) {
                const int h = zlist[k];
                const int hq = h >> 5, hb = h & 31;
                c0 -= (wT[(size_t)(d + 0) * HW + hq] >> hb) & 1;
                c1 -= (wT[(size_t)(d + 1) * HW + hq] >> hb) & 1;
                c2 -= (wT[(size_t)(d + 2) * HW + hq] >> hb) & 1;
                c3 -= (wT[(size_t)(d + 3) * HW + hq] >> hb) & 1;
            }
            float4 o;
            o.x = ((float)c0 + b3.x > 1.0f) ? 1.0f : 0.0f;
            o.y = ((float)c1 + b3.y > 1.0f) ? 1.0f : 0.0f;
            o.z = ((float)c2 + b3.z > 1.0f) ? 1.0f : 0.0f;
            o.w = ((float)c3 + b3.w > 1.0f) ? 1.0f : 0.0f;
            dst4[d4] = o;
        }
    }

    // ---- Phase 5: classifier (deterministic double accumulation) ----
    double corr = 0.0;
    for (int k = 0; k < znum; k++)
        corr += (double)clf[(size_t)t * HV + zlist[k]];
    out_class[(size_t)b * LV + t] = (float)(rowsum[t] - corr);
}

// ---------------------------------------------------------------------------
// Launch.  Output layout: [output (B*D) | classification (B*L) | z (B*H)].
// ---------------------------------------------------------------------------
extern "C" void kernel_launch(void* const* d_in, const int* in_sizes, int n_in,
                              void* d_out, int out_size) {
    const float* x     = (const float*)d_in[0];
    const float* w     = (const float*)d_in[1];
    const float* bias0 = (const float*)d_in[2];
    const float* bias3 = (const float*)d_in[3];
    const float* clf   = (const float*)d_in[4];

    float* out        = (float*)d_out;
    float* out_output = out;
    float* out_class  = out + (size_t)BV * DV;
    float* out_z      = out + (size_t)BV * DV + (size_t)BV * LV;

    uint32_t* wT;
    int* colsum;
    double* rowsum;
    float* basef;
    cudaGetSymbolAddress((void**)&wT, g_wT_bits);
    cudaGetSymbolAddress((void**)&colsum, g_colsum);
    cudaGetSymbolAddress((void**)&rowsum, g_rowsum);
    cudaGetSymbolAddress((void**)&basef, g_basef);

    // 0) zero the one accumulator that needs it
    cudaMemsetAsync(colsum, 0, DV * sizeof(int));

    // 1) fused prep: pack w -> wT + colsum  |  clf row sums
    prep_kernel<<<4096 + LV, 256>>>(w, clf, wT, colsum, rowsum);

    // 1b) thresholded base reconstruction row
    base_row_kernel<<<DV / 256, 256>>>(colsum, bias3, basef);

    // 2) fused main: sparse-scan z -> recon output + classification, per row
    main_kernel<<<BV, 128>>>(x, wT, colsum, bias0, bias3, clf, rowsum, basef,
                             out_output, out_class, out_z);
}